// round 12
// baseline (speedup 1.0000x reference)
#include <cuda_runtime.h>
#include <cuda_bf16.h>
#include <math.h>
#include <stdint.h>

#define B_ 4
#define S_ 2048
#define HID_ 2048
#define H_ 16
#define KV_ 4
#define D_ 128
#define ROT_ 32
#define NEG_ (-1000000000.0f)
#define SCALE_ 0.08838834764831845f   // D^-0.5
#define NQKV 5120                     // merged projection width

// ---------------- scratch (device globals; no allocations allowed) ----------
__device__ float g_qkv  [(size_t)B_*S_*NQKV];      // [M, 5120] q|gate|k|v
__device__ __nv_bfloat16 g_hhi[(size_t)B_*S_*HID_];
__device__ __nv_bfloat16 g_hlo[(size_t)B_*S_*HID_];
__device__ __nv_bfloat16 g_wqkvhi[(size_t)HID_*NQKV];
__device__ __nv_bfloat16 g_wqkvlo[(size_t)HID_*NQKV];
__device__ __nv_bfloat16 g_wohi[(size_t)H_*D_*HID_];
__device__ __nv_bfloat16 g_wolo[(size_t)H_*D_*HID_];
__device__ __nv_bfloat16 g_qhi[(size_t)B_*H_*S_*D_];
__device__ __nv_bfloat16 g_qlo[(size_t)B_*H_*S_*D_];
__device__ __nv_bfloat16 g_khi[(size_t)B_*KV_*S_*D_];
__device__ __nv_bfloat16 g_klo[(size_t)B_*KV_*S_*D_];
__device__ __nv_bfloat16 g_vhi[(size_t)B_*KV_*S_*D_];
__device__ __nv_bfloat16 g_vlo[(size_t)B_*KV_*S_*D_];
__device__ __nv_bfloat16 g_ghi[(size_t)B_*S_*H_*D_];
__device__ __nv_bfloat16 g_glo[(size_t)B_*S_*H_*D_];

// ---------------- mma helpers ------------------------------------------------
__device__ __forceinline__ uint32_t smem_u32(const void* p) {
    return (uint32_t)__cvta_generic_to_shared(p);
}
__device__ __forceinline__ void ldm_x4(uint32_t* r, uint32_t addr) {
    asm volatile("ldmatrix.sync.aligned.m8n8.x4.shared.b16 {%0,%1,%2,%3}, [%4];\n"
                 : "=r"(r[0]), "=r"(r[1]), "=r"(r[2]), "=r"(r[3]) : "r"(addr));
}
__device__ __forceinline__ void ldm_x4_t(uint32_t* r, uint32_t addr) {
    asm volatile("ldmatrix.sync.aligned.m8n8.x4.trans.shared.b16 {%0,%1,%2,%3}, [%4];\n"
                 : "=r"(r[0]), "=r"(r[1]), "=r"(r[2]), "=r"(r[3]) : "r"(addr));
}
__device__ __forceinline__ void mma_bf16(float* c, const uint32_t* a,
                                         uint32_t b0, uint32_t b1) {
    asm volatile(
        "mma.sync.aligned.m16n8k16.row.col.f32.bf16.bf16.f32 "
        "{%0,%1,%2,%3}, {%4,%5,%6,%7}, {%8,%9}, {%0,%1,%2,%3};\n"
        : "+f"(c[0]), "+f"(c[1]), "+f"(c[2]), "+f"(c[3])
        : "r"(a[0]), "r"(a[1]), "r"(a[2]), "r"(a[3]), "r"(b0), "r"(b1));
}
__device__ __forceinline__ void mma_bf16_s(float* c, uint32_t a0, uint32_t a1,
                                           uint32_t a2, uint32_t a3,
                                           uint32_t b0, uint32_t b1) {
    asm volatile(
        "mma.sync.aligned.m16n8k16.row.col.f32.bf16.bf16.f32 "
        "{%0,%1,%2,%3}, {%4,%5,%6,%7}, {%8,%9}, {%0,%1,%2,%3};\n"
        : "+f"(c[0]), "+f"(c[1]), "+f"(c[2]), "+f"(c[3])
        : "r"(a0), "r"(a1), "r"(a2), "r"(a3), "r"(b0), "r"(b1));
}
__device__ __forceinline__ uint32_t bf2_u32(__nv_bfloat162 v) {
    return *reinterpret_cast<uint32_t*>(&v);
}
__device__ __forceinline__ void cpa16(uint32_t dst, const void* src) {
    asm volatile("cp.async.cg.shared.global [%0], [%1], 16;\n"
                 :: "r"(dst), "l"(src));
}

// ---------------- split fp32 -> bf16 hi/lo (contiguous) ----------------------
__global__ __launch_bounds__(256)
void split_kernel(const float* __restrict__ src, __nv_bfloat16* __restrict__ hi,
                  __nv_bfloat16* __restrict__ lo) {
    size_t i = (size_t)blockIdx.x * 256 + threadIdx.x;
    float4 v = ((const float4*)src)[i];
    __nv_bfloat162 h0 = __floats2bfloat162_rn(v.x, v.y);
    __nv_bfloat162 h1 = __floats2bfloat162_rn(v.z, v.w);
    __nv_bfloat162 l0 = __floats2bfloat162_rn(v.x - __bfloat162float(h0.x),
                                              v.y - __bfloat162float(h0.y));
    __nv_bfloat162 l1 = __floats2bfloat162_rn(v.z - __bfloat162float(h1.x),
                                              v.w - __bfloat162float(h1.y));
    ((uint2*)hi)[i] = make_uint2(bf2_u32(h0), bf2_u32(h1));
    ((uint2*)lo)[i] = make_uint2(bf2_u32(l0), bf2_u32(l1));
}

// ---------------- split with column offset into merged weight buffer --------
__global__ __launch_bounds__(256)
void split_off_kernel(const float* __restrict__ src, __nv_bfloat16* __restrict__ hi,
                      __nv_bfloat16* __restrict__ lo, int ncols, int coloff) {
    size_t i = (size_t)blockIdx.x * 256 + threadIdx.x;   // float4 index in src
    int c4 = ncols >> 2;
    int row = (int)(i / c4), col = (int)(i % c4) << 2;
    float4 v = ((const float4*)src)[i];
    __nv_bfloat162 h0 = __floats2bfloat162_rn(v.x, v.y);
    __nv_bfloat162 h1 = __floats2bfloat162_rn(v.z, v.w);
    __nv_bfloat162 l0 = __floats2bfloat162_rn(v.x - __bfloat162float(h0.x),
                                              v.y - __bfloat162float(h0.y));
    __nv_bfloat162 l1 = __floats2bfloat162_rn(v.z - __bfloat162float(h1.x),
                                              v.w - __bfloat162float(h1.y));
    size_t o = ((size_t)row * NQKV + coloff + col) >> 2;   // uint2 index
    ((uint2*)hi)[o] = make_uint2(bf2_u32(h0), bf2_u32(h1));
    ((uint2*)lo)[o] = make_uint2(bf2_u32(l0), bf2_u32(l1));
}

// ---------------- bf16x3 tensor-core GEMM, 128x128x32, 256 thr, 2-stage -----
#define ASTR 40
#define BSTR 136
#define A_ELE (128*ASTR)
#define B_ELE (32*BSTR)
#define STG_ELE (2*A_ELE + 2*B_ELE)
#define GSMEM (2*STG_ELE*2)

__global__ __launch_bounds__(256)
void gemm_bf16p(const __nv_bfloat16* __restrict__ Ahi, const __nv_bfloat16* __restrict__ Alo,
                const __nv_bfloat16* __restrict__ Bhi, const __nv_bfloat16* __restrict__ Blo,
                float* __restrict__ C, int M, int N, int K) {
    extern __shared__ __nv_bfloat16 gsm[];
    int tid = threadIdx.x;
    int warp = tid >> 5, lane = tid & 31;
    int wm = (warp >> 2) * 64;
    int wn = (warp & 3) * 32;

    const __nv_bfloat16* Abh = Ahi + (size_t)blockIdx.y * 128 * K;
    const __nv_bfloat16* Abl = Alo + (size_t)blockIdx.y * 128 * K;
    const __nv_bfloat16* Bbh = Bhi + (size_t)blockIdx.x * 128;
    const __nv_bfloat16* Bbl = Blo + (size_t)blockIdx.x * 128;

    float acc[4][4][4];
    #pragma unroll
    for (int mt = 0; mt < 4; mt++)
        #pragma unroll
        for (int nt = 0; nt < 4; nt++)
            #pragma unroll
            for (int i = 0; i < 4; i++) acc[mt][nt][i] = 0.f;

    int KT = K >> 5;

    auto issue = [&](int kt, int st) {
        __nv_bfloat16* s = gsm + st * STG_ELE;
        int k0 = kt << 5;
        #pragma unroll
        for (int c = tid; c < 512; c += 256) {
            int row = c >> 2, col = (c & 3) << 3;
            size_t g = (size_t)row * K + k0 + col;
            cpa16(smem_u32(s + row * ASTR + col), Abh + g);
            cpa16(smem_u32(s + A_ELE + row * ASTR + col), Abl + g);
        }
        #pragma unroll
        for (int c = tid; c < 512; c += 256) {
            int row = c >> 4, col = (c & 15) << 3;
            size_t g = (size_t)(k0 + row) * N + col;
            cpa16(smem_u32(s + 2*A_ELE + row * BSTR + col), Bbh + g);
            cpa16(smem_u32(s + 2*A_ELE + B_ELE + row * BSTR + col), Bbl + g);
        }
        asm volatile("cp.async.commit_group;\n" ::: "memory");
    };

    issue(0, 0);
    for (int kt = 0; kt < KT; kt++) {
        asm volatile("cp.async.wait_group 0;\n" ::: "memory");
        __syncthreads();
        if (kt + 1 < KT) issue(kt + 1, (kt + 1) & 1);

        __nv_bfloat16* s = gsm + (kt & 1) * STG_ELE;
        __nv_bfloat16* sAhi = s;
        __nv_bfloat16* sAlo = s + A_ELE;
        __nv_bfloat16* sBhi = s + 2*A_ELE;
        __nv_bfloat16* sBlo = s + 2*A_ELE + B_ELE;

        #pragma unroll
        for (int ks = 0; ks < 2; ks++) {
            int kk = ks * 16;
            uint32_t ahi[4][4], alo[4][4];
            #pragma unroll
            for (int mt = 0; mt < 4; mt++) {
                int row = wm + mt * 16 + (lane & 15);
                int col = kk + ((lane >> 4) << 3);
                ldm_x4(ahi[mt], smem_u32(&sAhi[row * ASTR + col]));
                ldm_x4(alo[mt], smem_u32(&sAlo[row * ASTR + col]));
            }
            uint32_t bhi[2][4], blo[2][4];
            #pragma unroll
            for (int nc = 0; nc < 2; nc++) {
                int row = kk + (lane & 15);
                int col = wn + nc * 16 + ((lane >> 4) << 3);
                ldm_x4_t(bhi[nc], smem_u32(&sBhi[row * BSTR + col]));
                ldm_x4_t(blo[nc], smem_u32(&sBlo[row * BSTR + col]));
            }
            #pragma unroll
            for (int mt = 0; mt < 4; mt++) {
                #pragma unroll
                for (int nt = 0; nt < 4; nt++) {
                    int nc = nt >> 1, off = (nt & 1) << 1;
                    mma_bf16(acc[mt][nt], ahi[mt], bhi[nc][off], bhi[nc][off + 1]);
                    mma_bf16(acc[mt][nt], ahi[mt], blo[nc][off], blo[nc][off + 1]);
                    mma_bf16(acc[mt][nt], alo[mt], bhi[nc][off], bhi[nc][off + 1]);
                }
            }
        }
        __syncthreads();
    }

    float* Cb = C + (size_t)blockIdx.y * 128 * N + (size_t)blockIdx.x * 128;
    #pragma unroll
    for (int mt = 0; mt < 4; mt++) {
        #pragma unroll
        for (int nt = 0; nt < 4; nt++) {
            int r = wm + mt * 16 + (lane >> 2);
            int c = wn + nt * 8 + ((lane & 3) << 1);
            *(float2*)&Cb[(size_t)r * N + c] = make_float2(acc[mt][nt][0], acc[mt][nt][1]);
            *(float2*)&Cb[(size_t)(r + 8) * N + c] = make_float2(acc[mt][nt][2], acc[mt][nt][3]);
        }
    }
}

// ---------------- merged RMSNorm + RoPE, parallel over head groups ----------
// grid (M, 5): y in 0..3 -> Q heads 4y..4y+3;  y == 4 -> all KV heads.
__global__ __launch_bounds__(128)
void norm_rope_kernel(const float* __restrict__ cosb, const float* __restrict__ sinb,
                      const float* __restrict__ qw, const float* __restrict__ kw) {
    int bs = blockIdx.x, grp = blockIdx.y, d = threadIdx.x;
    float cthis = 0.f, sthis = 0.f;
    if (d < ROT_) {
        cthis = cosb[(size_t)bs * ROT_ + d];
        sthis = sinb[(size_t)bs * ROT_ + d];
    }
    int b = bs / S_, s = bs % S_;
    int warp = d >> 5, lane = d & 31;
    __shared__ float ws[4];
    const float* rowp = g_qkv + (size_t)bs * NQKV;

    if (grp < 4) {
        float qwd = 1.f + qw[d];
        #pragma unroll
        for (int hh = 0; hh < 4; hh++) {
            int h = grp * 4 + hh;
            float x = rowp[h * (2*D_) + d];
            float v = x * x;
            #pragma unroll
            for (int off = 16; off; off >>= 1) v += __shfl_xor_sync(0xffffffffu, v, off);
            if (lane == 0) ws[warp] = v;
            __syncthreads();
            float tot = ws[0] + ws[1] + ws[2] + ws[3];
            __syncthreads();

            float xn = x * rsqrtf(tot * (1.f/128.f) + 1e-6f) * qwd;
            float o = xn;
            if (d < ROT_) {
                float xp = __shfl_xor_sync(0xffffffffu, xn, 16);
                float rot = (d < 16) ? -xp : xp;
                o = xn * cthis + rot * sthis;
            }
            o *= SCALE_;   // fold softmax scale into Q
            size_t idx = (((size_t)b * H_ + h) * S_ + s) * D_ + d;
            __nv_bfloat16 hi = __float2bfloat16(o);
            g_qhi[idx] = hi;
            g_qlo[idx] = __float2bfloat16(o - __bfloat162float(hi));
        }
    } else {
        float kwd = 1.f + kw[d];
        #pragma unroll
        for (int kv = 0; kv < KV_; kv++) {
            float x = rowp[4096 + kv * D_ + d];
            float v = x * x;
            #pragma unroll
            for (int off = 16; off; off >>= 1) v += __shfl_xor_sync(0xffffffffu, v, off);
            if (lane == 0) ws[warp] = v;
            __syncthreads();
            float tot = ws[0] + ws[1] + ws[2] + ws[3];
            __syncthreads();

            float xn = x * rsqrtf(tot * (1.f/128.f) + 1e-6f) * kwd;
            float o = xn;
            if (d < ROT_) {
                float xp = __shfl_xor_sync(0xffffffffu, xn, 16);
                float rot = (d < 16) ? -xp : xp;
                o = xn * cthis + rot * sthis;
            }
            size_t oidx = (((size_t)b * KV_ + kv) * S_ + s) * D_ + d;
            __nv_bfloat16 khi = __float2bfloat16(o);
            g_khi[oidx] = khi;
            g_klo[oidx] = __float2bfloat16(o - __bfloat162float(khi));
            float vv = rowp[4608 + kv * D_ + d];
            __nv_bfloat16 vhi = __float2bfloat16(vv);
            g_vhi[oidx] = vhi;
            g_vlo[oidx] = __float2bfloat16(vv - __bfloat162float(vhi));
        }
    }
}

// ---------------- tensor-core flash attention, cp.async double-buffered K/V -
#define AQS 136
#define KVST (4*64*AQS)                     // elements per KV stage
#define ATT_SMEM ((2*128*AQS + 2*KVST) * 2) // bytes

__global__ __launch_bounds__(256)
void attn_mma_kernel() {
    extern __shared__ __align__(16) __nv_bfloat16 smA[];
    __nv_bfloat16* sQh = smA;
    __nv_bfloat16* sQl = sQh + 128 * AQS;
    __nv_bfloat16* sKV = sQl + 128 * AQS;   // 2 stages x [Kh|Kl|Vh|Vl]

    int tid = threadIdx.x, warp = tid >> 5, lane = tid & 31;
    int bh = blockIdx.x;
    int qt = (int)gridDim.y - 1 - (int)blockIdx.y;   // heavy blocks first (LPT)
    int b = bh >> 4, h = bh & 15, kvh = h >> 2;

    size_t qoff = ((size_t)bh * S_ + (size_t)qt * 128) * D_;
    size_t kvoff = ((size_t)(b * KV_ + kvh) * S_) * D_;

    for (int i = tid; i < 2048; i += 256) {
        int r = i >> 4, c = (i & 15) << 3;
        *(uint4*)&sQh[r * AQS + c] = *(const uint4*)&g_qhi[qoff + (size_t)r * D_ + c];
        *(uint4*)&sQl[r * AQS + c] = *(const uint4*)&g_qlo[qoff + (size_t)r * D_ + c];
    }

    auto issue_kv = [&](int kt, int st) {
        __nv_bfloat16* s = sKV + st * KVST;
        size_t koff = kvoff + (size_t)kt * 64 * D_;
        #pragma unroll
        for (int i = tid; i < 1024; i += 256) {
            int r = i >> 4, c = (i & 15) << 3;
            size_t g = koff + (size_t)r * D_ + c;
            int sidx = r * AQS + c;
            cpa16(smem_u32(s + sidx), &g_khi[g]);
            cpa16(smem_u32(s + 64*AQS + sidx), &g_klo[g]);
            cpa16(smem_u32(s + 2*64*AQS + sidx), &g_vhi[g]);
            cpa16(smem_u32(s + 3*64*AQS + sidx), &g_vlo[g]);
        }
    };

    float acc[16][4];
    #pragma unroll
    for (int ot = 0; ot < 16; ot++)
        #pragma unroll
        for (int i = 0; i < 4; i++) acc[ot][i] = 0.f;
    float m0 = -1e30f, m1 = -1e30f, l0 = 0.f, l1 = 0.f;

    int nkt = 2 * qt + 2;
    issue_kv(0, 0);
    asm volatile("cp.async.commit_group;\n" ::: "memory");

    for (int kt = 0; kt < nkt; kt++) {
        if (kt + 1 < nkt) issue_kv(kt + 1, (kt + 1) & 1);
        asm volatile("cp.async.commit_group;\n" ::: "memory");
        asm volatile("cp.async.wait_group 1;\n" ::: "memory");
        __syncthreads();

        // warp-uniform: skip tiles that are entirely above the diagonal
        // (every col > every row -> all P = exp(NEG - m) = 0, no contribution)
        if (kt * 64 > qt * 128 + warp * 16 + 15) {
            __syncthreads();
            continue;
        }

        __nv_bfloat16* s = sKV + (kt & 1) * KVST;
        __nv_bfloat16* sKh = s;
        __nv_bfloat16* sKl = s + 64*AQS;
        __nv_bfloat16* sVh = s + 2*64*AQS;
        __nv_bfloat16* sVl = s + 3*64*AQS;

        float sc[8][4];
        #pragma unroll
        for (int nt = 0; nt < 8; nt++)
            #pragma unroll
            for (int i = 0; i < 4; i++) sc[nt][i] = 0.f;

        #pragma unroll
        for (int kk = 0; kk < 8; kk++) {
            uint32_t ah[4], al[4];
            int qidx = (warp * 16 + (lane & 15)) * AQS + kk * 16 + ((lane >> 4) << 3);
            ldm_x4(ah, smem_u32(&sQh[qidx]));
            ldm_x4(al, smem_u32(&sQl[qidx]));
            #pragma unroll
            for (int nc = 0; nc < 4; nc++) {
                uint32_t kh4[4], kl4[4];
                int kidx = (nc * 16 + (lane & 15)) * AQS + kk * 16 + ((lane >> 4) << 3);
                ldm_x4(kh4, smem_u32(&sKh[kidx]));
                ldm_x4(kl4, smem_u32(&sKl[kidx]));
                #pragma unroll
                for (int hf = 0; hf < 2; hf++) {
                    int nt = nc * 2 + hf;
                    mma_bf16(sc[nt], ah, kh4[hf], kh4[hf + 2]);
                    mma_bf16(sc[nt], ah, kl4[hf], kl4[hf + 2]);
                    mma_bf16(sc[nt], al, kh4[hf], kh4[hf + 2]);
                }
            }
        }

        // ---- softmax (scale pre-folded into Q); mask only near the diagonal
        int row0 = qt * 128 + warp * 16 + (lane >> 2);
        int col0 = kt * 64 + ((lane & 3) << 1);
        float ml0 = -1e30f, ml1 = -1e30f;
        bool needmask = (kt * 64 + 63) > (qt * 128 + warp * 16);
        if (needmask) {
            #pragma unroll
            for (int nt = 0; nt < 8; nt++) {
                int c0 = col0 + nt * 8;
                float v0 = sc[nt][0] + ((c0    ) > row0     ? NEG_ : 0.f);
                float v1 = sc[nt][1] + ((c0 + 1) > row0     ? NEG_ : 0.f);
                float v2 = sc[nt][2] + ((c0    ) > row0 + 8 ? NEG_ : 0.f);
                float v3 = sc[nt][3] + ((c0 + 1) > row0 + 8 ? NEG_ : 0.f);
                sc[nt][0] = v0; sc[nt][1] = v1; sc[nt][2] = v2; sc[nt][3] = v3;
                ml0 = fmaxf(ml0, fmaxf(v0, v1));
                ml1 = fmaxf(ml1, fmaxf(v2, v3));
            }
        } else {
            #pragma unroll
            for (int nt = 0; nt < 8; nt++) {
                ml0 = fmaxf(ml0, fmaxf(sc[nt][0], sc[nt][1]));
                ml1 = fmaxf(ml1, fmaxf(sc[nt][2], sc[nt][3]));
            }
        }
        ml0 = fmaxf(ml0, __shfl_xor_sync(0xffffffffu, ml0, 1));
        ml0 = fmaxf(ml0, __shfl_xor_sync(0xffffffffu, ml0, 2));
        ml1 = fmaxf(ml1, __shfl_xor_sync(0xffffffffu, ml1, 1));
        ml1 = fmaxf(ml1, __shfl_xor_sync(0xffffffffu, ml1, 2));
        float nm0 = fmaxf(m0, ml0), nm1 = fmaxf(m1, ml1);
        float corr0 = __expf(m0 - nm0), corr1 = __expf(m1 - nm1);
        m0 = nm0; m1 = nm1;

        uint32_t ph[8][2], pl[8][2];
        float sum0 = 0.f, sum1 = 0.f;
        #pragma unroll
        for (int nt = 0; nt < 8; nt++) {
            float p0 = __expf(sc[nt][0] - nm0);
            float p1 = __expf(sc[nt][1] - nm0);
            float p2 = __expf(sc[nt][2] - nm1);
            float p3 = __expf(sc[nt][3] - nm1);
            sum0 += p0 + p1; sum1 += p2 + p3;
            __nv_bfloat162 h01 = __floats2bfloat162_rn(p0, p1);
            __nv_bfloat162 h23 = __floats2bfloat162_rn(p2, p3);
            ph[nt][0] = bf2_u32(h01);
            ph[nt][1] = bf2_u32(h23);
            __nv_bfloat162 l01 = __floats2bfloat162_rn(p0 - __bfloat162float(h01.x),
                                                       p1 - __bfloat162float(h01.y));
            __nv_bfloat162 l23 = __floats2bfloat162_rn(p2 - __bfloat162float(h23.x),
                                                       p3 - __bfloat162float(h23.y));
            pl[nt][0] = bf2_u32(l01);
            pl[nt][1] = bf2_u32(l23);
        }
        sum0 += __shfl_xor_sync(0xffffffffu, sum0, 1);
        sum0 += __shfl_xor_sync(0xffffffffu, sum0, 2);
        sum1 += __shfl_xor_sync(0xffffffffu, sum1, 1);
        sum1 += __shfl_xor_sync(0xffffffffu, sum1, 2);
        l0 = l0 * corr0 + sum0;
        l1 = l1 * corr1 + sum1;
        #pragma unroll
        for (int ot = 0; ot < 16; ot++) {
            acc[ot][0] *= corr0; acc[ot][1] *= corr0;
            acc[ot][2] *= corr1; acc[ot][3] *= corr1;
        }

        #pragma unroll
        for (int k2 = 0; k2 < 4; k2++) {
            uint32_t a0 = ph[2*k2][0], a1 = ph[2*k2][1];
            uint32_t a2 = ph[2*k2+1][0], a3 = ph[2*k2+1][1];
            uint32_t e0 = pl[2*k2][0], e1 = pl[2*k2][1];
            uint32_t e2 = pl[2*k2+1][0], e3 = pl[2*k2+1][1];
            #pragma unroll
            for (int nc = 0; nc < 8; nc++) {
                uint32_t vh4[4], vl4[4];
                int vidx = (k2 * 16 + (lane & 15)) * AQS + nc * 16 + ((lane >> 4) << 3);
                ldm_x4_t(vh4, smem_u32(&sVh[vidx]));
                ldm_x4_t(vl4, smem_u32(&sVl[vidx]));
                #pragma unroll
                for (int hf = 0; hf < 2; hf++) {
                    int ot = nc * 2 + hf, of = hf * 2;
                    mma_bf16_s(acc[ot], a0, a1, a2, a3, vh4[of], vh4[of + 1]);
                    mma_bf16_s(acc[ot], a0, a1, a2, a3, vl4[of], vl4[of + 1]);
                    mma_bf16_s(acc[ot], e0, e1, e2, e3, vh4[of], vh4[of + 1]);
                }
            }
        }
        __syncthreads();
    }

    // ---- epilogue: normalize, gate, write bf16 hi/lo gated output
    float inv0 = 1.f / l0, inv1 = 1.f / l1;
    int srow = qt * 128 + warp * 16 + (lane >> 2);
    #pragma unroll
    for (int rp = 0; rp < 2; rp++) {
        int s = srow + rp * 8;
        size_t bs = (size_t)b * S_ + s;
        float inv = rp ? inv1 : inv0;
        #pragma unroll
        for (int ot = 0; ot < 16; ot++) {
            int c0 = ot * 8 + ((lane & 3) << 1);
            float2 g2 = *(const float2*)&g_qkv[bs * (size_t)NQKV + h * (2*D_) + D_ + c0];
            float o0 = acc[ot][rp*2    ] * inv * (1.f / (1.f + __expf(-g2.x)));
            float o1 = acc[ot][rp*2 + 1] * inv * (1.f / (1.f + __expf(-g2.y)));
            __nv_bfloat162 hi2 = __floats2bfloat162_rn(o0, o1);
            __nv_bfloat162 lo2 = __floats2bfloat162_rn(o0 - __bfloat162float(hi2.x),
                                                       o1 - __bfloat162float(hi2.y));
            size_t oi = bs * (size_t)(H_*D_) + h * D_ + c0;
            *(uint32_t*)&g_ghi[oi] = bf2_u32(hi2);
            *(uint32_t*)&g_glo[oi] = bf2_u32(lo2);
        }
    }
}

// ---------------- launch ----------------------------------------------------
extern "C" void kernel_launch(void* const* d_in, const int* in_sizes, int n_in,
                              void* d_out, int out_size) {
    const float* hidden = (const float*)d_in[0];
    const float* cosb   = (const float*)d_in[1];
    const float* sinb   = (const float*)d_in[2];
    // d_in[3] = attention_mask (pure causal; computed arithmetically)
    const float* wq     = (const float*)d_in[4];
    const float* wk     = (const float*)d_in[5];
    const float* wv     = (const float*)d_in[6];
    const float* wo     = (const float*)d_in[7];
    const float* qnw    = (const float*)d_in[8];
    const float* knw    = (const float*)d_in[9];
    float* out = (float*)d_out;

    float* qkv;
    cudaGetSymbolAddress((void**)&qkv, g_qkv);
    __nv_bfloat16 *hhi, *hlo, *wqkvhi, *wqkvlo, *wohi, *wolo, *ghi, *glo;
    cudaGetSymbolAddress((void**)&hhi,    g_hhi);
    cudaGetSymbolAddress((void**)&hlo,    g_hlo);
    cudaGetSymbolAddress((void**)&wqkvhi, g_wqkvhi);
    cudaGetSymbolAddress((void**)&wqkvlo, g_wqkvlo);
    cudaGetSymbolAddress((void**)&wohi,   g_wohi);
    cudaGetSymbolAddress((void**)&wolo,   g_wolo);
    cudaGetSymbolAddress((void**)&ghi,    g_ghi);
    cudaGetSymbolAddress((void**)&glo,    g_glo);

    cudaFuncSetAttribute(attn_mma_kernel,
                         cudaFuncAttributeMaxDynamicSharedMemorySize, ATT_SMEM);
    cudaFuncSetAttribute(gemm_bf16p,
                         cudaFuncAttributeMaxDynamicSharedMemorySize, GSMEM);

    const int M = B_ * S_;   // 8192

    // pre-split fp32 -> bf16 hi/lo
    split_kernel<<<(B_*S_*HID_)/1024, 256>>>(hidden, hhi, hlo);
    split_off_kernel<<<(HID_*H_*2*D_)/1024, 256>>>(wq, wqkvhi, wqkvlo, H_*2*D_, 0);
    split_off_kernel<<<(HID_*KV_*D_)/1024, 256>>>(wk, wqkvhi, wqkvlo, KV_*D_, 4096);
    split_off_kernel<<<(HID_*KV_*D_)/1024, 256>>>(wv, wqkvhi, wqkvlo, KV_*D_, 4608);
    split_kernel<<<(H_*D_*HID_)/1024, 256>>>(wo, wohi, wolo);

    // merged QKV projection
    gemm_bf16p<<<dim3(NQKV/128, M/128), 256, GSMEM>>>(hhi, hlo, wqkvhi, wqkvlo, qkv, M, NQKV, HID_);

    // norms + rope -> bf16 hi/lo (parallel over head groups)
    norm_rope_kernel<<<dim3(M, 5), 128>>>(cosb, sinb, qnw, knw);

    // tensor-core attention (+ fused sigmoid gate, bf16 hi/lo out)
    attn_mma_kernel<<<dim3(B_*H_, S_/128), 256, ATT_SMEM>>>();

    // output projection
    gemm_bf16p<<<dim3(HID_/128, M/128), 256, GSMEM>>>(ghi, glo, wohi, wolo, out, M, HID_, H_*D_);
}

// round 14
// speedup vs baseline: 1.5992x; 1.5992x over previous
#include <cuda_runtime.h>
#include <cuda_bf16.h>
#include <cuda_fp16.h>
#include <math.h>
#include <stdint.h>

#define B_ 4
#define S_ 2048
#define HID_ 2048
#define H_ 16
#define KV_ 4
#define D_ 128
#define ROT_ 32
#define NEG_ (-1000000000.0f)
#define SCALE_ 0.08838834764831845f   // D^-0.5
#define NQKV 5120                     // merged projection width

// ---------------- scratch (device globals; no allocations allowed) ----------
__device__ float g_qkv  [(size_t)B_*S_*NQKV];      // [M, 5120] q|gate|k|v
__device__ __half g_hh   [(size_t)B_*S_*HID_];     // hidden fp16
__device__ __half g_wqkv [(size_t)HID_*NQKV];      // merged W fp16 [K, 5120]
__device__ __half g_wo   [(size_t)H_*D_*HID_];     // Wo fp16 [1024*2... [2048,2048]
__device__ __half g_gated[(size_t)B_*S_*H_*D_];    // gated attn fp16
__device__ __nv_bfloat16 g_qhi[(size_t)B_*H_*S_*D_];
__device__ __nv_bfloat16 g_qlo[(size_t)B_*H_*S_*D_];
__device__ __nv_bfloat16 g_khi[(size_t)B_*KV_*S_*D_];
__device__ __nv_bfloat16 g_klo[(size_t)B_*KV_*S_*D_];
__device__ __nv_bfloat16 g_vhi[(size_t)B_*KV_*S_*D_];
__device__ __nv_bfloat16 g_vlo[(size_t)B_*KV_*S_*D_];

// ---------------- helpers -----------------------------------------------------
__device__ __forceinline__ uint32_t smem_u32(const void* p) {
    return (uint32_t)__cvta_generic_to_shared(p);
}
__device__ __forceinline__ void ldm_x4(uint32_t* r, uint32_t addr) {
    asm volatile("ldmatrix.sync.aligned.m8n8.x4.shared.b16 {%0,%1,%2,%3}, [%4];\n"
                 : "=r"(r[0]), "=r"(r[1]), "=r"(r[2]), "=r"(r[3]) : "r"(addr));
}
__device__ __forceinline__ void ldm_x4_t(uint32_t* r, uint32_t addr) {
    asm volatile("ldmatrix.sync.aligned.m8n8.x4.trans.shared.b16 {%0,%1,%2,%3}, [%4];\n"
                 : "=r"(r[0]), "=r"(r[1]), "=r"(r[2]), "=r"(r[3]) : "r"(addr));
}
__device__ __forceinline__ void mma_bf16(float* c, const uint32_t* a,
                                         uint32_t b0, uint32_t b1) {
    asm volatile(
        "mma.sync.aligned.m16n8k16.row.col.f32.bf16.bf16.f32 "
        "{%0,%1,%2,%3}, {%4,%5,%6,%7}, {%8,%9}, {%0,%1,%2,%3};\n"
        : "+f"(c[0]), "+f"(c[1]), "+f"(c[2]), "+f"(c[3])
        : "r"(a[0]), "r"(a[1]), "r"(a[2]), "r"(a[3]), "r"(b0), "r"(b1));
}
__device__ __forceinline__ void mma_bf16_s(float* c, uint32_t a0, uint32_t a1,
                                           uint32_t a2, uint32_t a3,
                                           uint32_t b0, uint32_t b1) {
    asm volatile(
        "mma.sync.aligned.m16n8k16.row.col.f32.bf16.bf16.f32 "
        "{%0,%1,%2,%3}, {%4,%5,%6,%7}, {%8,%9}, {%0,%1,%2,%3};\n"
        : "+f"(c[0]), "+f"(c[1]), "+f"(c[2]), "+f"(c[3])
        : "r"(a0), "r"(a1), "r"(a2), "r"(a3), "r"(b0), "r"(b1));
}
__device__ __forceinline__ void mma_f16(float* c, const uint32_t* a,
                                        uint32_t b0, uint32_t b1) {
    asm volatile(
        "mma.sync.aligned.m16n8k16.row.col.f32.f16.f16.f32 "
        "{%0,%1,%2,%3}, {%4,%5,%6,%7}, {%8,%9}, {%0,%1,%2,%3};\n"
        : "+f"(c[0]), "+f"(c[1]), "+f"(c[2]), "+f"(c[3])
        : "r"(a[0]), "r"(a[1]), "r"(a[2]), "r"(a[3]), "r"(b0), "r"(b1));
}
__device__ __forceinline__ uint32_t bf2_u32(__nv_bfloat162 v) {
    return *reinterpret_cast<uint32_t*>(&v);
}
__device__ __forceinline__ uint32_t h2_u32(__half2 v) {
    return *reinterpret_cast<uint32_t*>(&v);
}
__device__ __forceinline__ void cpa16(uint32_t dst, const void* src) {
    asm volatile("cp.async.cg.shared.global [%0], [%1], 16;\n"
                 :: "r"(dst), "l"(src));
}

// ---------------- convert fp32 -> fp16 (contiguous) ---------------------------
__global__ __launch_bounds__(256)
void conv_kernel(const float* __restrict__ src, __half* __restrict__ dst) {
    size_t i = (size_t)blockIdx.x * 256 + threadIdx.x;   // float4 index
    float4 v = ((const float4*)src)[i];
    __half2 h0 = __floats2half2_rn(v.x, v.y);
    __half2 h1 = __floats2half2_rn(v.z, v.w);
    ((uint2*)dst)[i] = make_uint2(h2_u32(h0), h2_u32(h1));
}

// ---------------- convert with column offset into merged weight buffer -------
__global__ __launch_bounds__(256)
void conv_off_kernel(const float* __restrict__ src, __half* __restrict__ dst,
                     int ncols, int coloff) {
    size_t i = (size_t)blockIdx.x * 256 + threadIdx.x;   // float4 index in src
    int c4 = ncols >> 2;
    int row = (int)(i / c4), col = (int)(i % c4) << 2;
    float4 v = ((const float4*)src)[i];
    __half2 h0 = __floats2half2_rn(v.x, v.y);
    __half2 h1 = __floats2half2_rn(v.z, v.w);
    size_t o = ((size_t)row * NQKV + coloff + col) >> 2;   // uint2 index
    ((uint2*)dst)[o] = make_uint2(h2_u32(h0), h2_u32(h1));
}

// ---------------- fp16 tensor-core GEMM, 128x128x32, 256 thr, 2-stage --------
#define ASTR 40
#define BSTR 136
#define A_ELE (128*ASTR)
#define B_ELE (32*BSTR)
#define FSTG (A_ELE + B_ELE)          // 9472 half elems per stage
#define GSMEMF (2*FSTG*2)             // 37888 bytes

__global__ __launch_bounds__(256)
void gemm_fp16(const __half* __restrict__ A, const __half* __restrict__ B,
               float* __restrict__ C, int M, int N, int K) {
    extern __shared__ __half fsm[];
    int tid = threadIdx.x;
    int warp = tid >> 5, lane = tid & 31;
    int wm = (warp >> 2) * 64;
    int wn = (warp & 3) * 32;

    const __half* Ab = A + (size_t)blockIdx.y * 128 * K;
    const __half* Bb = B + (size_t)blockIdx.x * 128;

    float acc[4][4][4];
    #pragma unroll
    for (int mt = 0; mt < 4; mt++)
        #pragma unroll
        for (int nt = 0; nt < 4; nt++)
            #pragma unroll
            for (int i = 0; i < 4; i++) acc[mt][nt][i] = 0.f;

    int KT = K >> 5;

    auto issue = [&](int kt, int st) {
        __half* s = fsm + st * FSTG;
        int k0 = kt << 5;
        #pragma unroll
        for (int c = tid; c < 512; c += 256) {
            int row = c >> 2, col = (c & 3) << 3;
            cpa16(smem_u32(s + row * ASTR + col), Ab + (size_t)row * K + k0 + col);
        }
        #pragma unroll
        for (int c = tid; c < 512; c += 256) {
            int row = c >> 4, col = (c & 15) << 3;
            cpa16(smem_u32(s + A_ELE + row * BSTR + col), Bb + (size_t)(k0 + row) * N + col);
        }
        asm volatile("cp.async.commit_group;\n" ::: "memory");
    };

    issue(0, 0);
    for (int kt = 0; kt < KT; kt++) {
        asm volatile("cp.async.wait_group 0;\n" ::: "memory");
        __syncthreads();
        if (kt + 1 < KT) issue(kt + 1, (kt + 1) & 1);

        __half* s = fsm + (kt & 1) * FSTG;
        __half* sA = s;
        __half* sB = s + A_ELE;

        #pragma unroll
        for (int ks = 0; ks < 2; ks++) {
            int kk = ks * 16;
            uint32_t af[4][4];
            #pragma unroll
            for (int mt = 0; mt < 4; mt++) {
                int row = wm + mt * 16 + (lane & 15);
                int col = kk + ((lane >> 4) << 3);
                ldm_x4(af[mt], smem_u32(&sA[row * ASTR + col]));
            }
            uint32_t bf[2][4];
            #pragma unroll
            for (int nc = 0; nc < 2; nc++) {
                int row = kk + (lane & 15);
                int col = wn + nc * 16 + ((lane >> 4) << 3);
                ldm_x4_t(bf[nc], smem_u32(&sB[row * BSTR + col]));
            }
            #pragma unroll
            for (int mt = 0; mt < 4; mt++) {
                #pragma unroll
                for (int nt = 0; nt < 4; nt++) {
                    int nc = nt >> 1, off = (nt & 1) << 1;
                    mma_f16(acc[mt][nt], af[mt], bf[nc][off], bf[nc][off + 1]);
                }
            }
        }
        __syncthreads();
    }

    float* Cb = C + (size_t)blockIdx.y * 128 * N + (size_t)blockIdx.x * 128;
    #pragma unroll
    for (int mt = 0; mt < 4; mt++) {
        #pragma unroll
        for (int nt = 0; nt < 4; nt++) {
            int r = wm + mt * 16 + (lane >> 2);
            int c = wn + nt * 8 + ((lane & 3) << 1);
            *(float2*)&Cb[(size_t)r * N + c] = make_float2(acc[mt][nt][0], acc[mt][nt][1]);
            *(float2*)&Cb[(size_t)(r + 8) * N + c] = make_float2(acc[mt][nt][2], acc[mt][nt][3]);
        }
    }
}

// ---------------- merged RMSNorm + RoPE, parallel over head groups ----------
// grid (M, 5): y in 0..3 -> Q heads 4y..4y+3;  y == 4 -> all KV heads.
__global__ __launch_bounds__(128)
void norm_rope_kernel(const float* __restrict__ cosb, const float* __restrict__ sinb,
                      const float* __restrict__ qw, const float* __restrict__ kw) {
    int bs = blockIdx.x, grp = blockIdx.y, d = threadIdx.x;
    float cthis = 0.f, sthis = 0.f;
    if (d < ROT_) {
        cthis = cosb[(size_t)bs * ROT_ + d];
        sthis = sinb[(size_t)bs * ROT_ + d];
    }
    int b = bs / S_, s = bs % S_;
    int warp = d >> 5, lane = d & 31;
    __shared__ float ws[4];
    const float* rowp = g_qkv + (size_t)bs * NQKV;

    if (grp < 4) {
        float qwd = 1.f + qw[d];
        #pragma unroll
        for (int hh = 0; hh < 4; hh++) {
            int h = grp * 4 + hh;
            float x = rowp[h * (2*D_) + d];
            float v = x * x;
            #pragma unroll
            for (int off = 16; off; off >>= 1) v += __shfl_xor_sync(0xffffffffu, v, off);
            if (lane == 0) ws[warp] = v;
            __syncthreads();
            float tot = ws[0] + ws[1] + ws[2] + ws[3];
            __syncthreads();

            float xn = x * rsqrtf(tot * (1.f/128.f) + 1e-6f) * qwd;
            float o = xn;
            if (d < ROT_) {
                float xp = __shfl_xor_sync(0xffffffffu, xn, 16);
                float rot = (d < 16) ? -xp : xp;
                o = xn * cthis + rot * sthis;
            }
            o *= SCALE_;
            size_t idx = (((size_t)b * H_ + h) * S_ + s) * D_ + d;
            __nv_bfloat16 hi = __float2bfloat16(o);
            g_qhi[idx] = hi;
            g_qlo[idx] = __float2bfloat16(o - __bfloat162float(hi));
        }
    } else {
        float kwd = 1.f + kw[d];
        #pragma unroll
        for (int kv = 0; kv < KV_; kv++) {
            float x = rowp[4096 + kv * D_ + d];
            float v = x * x;
            #pragma unroll
            for (int off = 16; off; off >>= 1) v += __shfl_xor_sync(0xffffffffu, v, off);
            if (lane == 0) ws[warp] = v;
            __syncthreads();
            float tot = ws[0] + ws[1] + ws[2] + ws[3];
            __syncthreads();

            float xn = x * rsqrtf(tot * (1.f/128.f) + 1e-6f) * kwd;
            float o = xn;
            if (d < ROT_) {
                float xp = __shfl_xor_sync(0xffffffffu, xn, 16);
                float rot = (d < 16) ? -xp : xp;
                o = xn * cthis + rot * sthis;
            }
            size_t oidx = (((size_t)b * KV_ + kv) * S_ + s) * D_ + d;
            __nv_bfloat16 khi = __float2bfloat16(o);
            g_khi[oidx] = khi;
            g_klo[oidx] = __float2bfloat16(o - __bfloat162float(khi));
            float vv = rowp[4608 + kv * D_ + d];
            __nv_bfloat16 vhi = __float2bfloat16(vv);
            g_vhi[oidx] = vhi;
            g_vlo[oidx] = __float2bfloat16(vv - __bfloat162float(vhi));
        }
    }
}

// ---------------- tensor-core flash attention, cp.async double-buffered K/V -
#define AQS 136
#define KVST (4*64*AQS)
#define ATT_SMEM ((2*128*AQS + 2*KVST) * 2)

__global__ __launch_bounds__(256)
void attn_mma_kernel() {
    extern __shared__ __align__(16) __nv_bfloat16 smA[];
    __nv_bfloat16* sQh = smA;
    __nv_bfloat16* sQl = sQh + 128 * AQS;
    __nv_bfloat16* sKV = sQl + 128 * AQS;

    int tid = threadIdx.x, warp = tid >> 5, lane = tid & 31;
    int bh = blockIdx.x;
    int qt = (int)gridDim.y - 1 - (int)blockIdx.y;   // LPT
    int b = bh >> 4, h = bh & 15, kvh = h >> 2;

    size_t qoff = ((size_t)bh * S_ + (size_t)qt * 128) * D_;
    size_t kvoff = ((size_t)(b * KV_ + kvh) * S_) * D_;

    for (int i = tid; i < 2048; i += 256) {
        int r = i >> 4, c = (i & 15) << 3;
        *(uint4*)&sQh[r * AQS + c] = *(const uint4*)&g_qhi[qoff + (size_t)r * D_ + c];
        *(uint4*)&sQl[r * AQS + c] = *(const uint4*)&g_qlo[qoff + (size_t)r * D_ + c];
    }

    auto issue_kv = [&](int kt, int st) {
        __nv_bfloat16* s = sKV + st * KVST;
        size_t koff = kvoff + (size_t)kt * 64 * D_;
        #pragma unroll
        for (int i = tid; i < 1024; i += 256) {
            int r = i >> 4, c = (i & 15) << 3;
            size_t g = koff + (size_t)r * D_ + c;
            int sidx = r * AQS + c;
            cpa16(smem_u32(s + sidx), &g_khi[g]);
            cpa16(smem_u32(s + 64*AQS + sidx), &g_klo[g]);
            cpa16(smem_u32(s + 2*64*AQS + sidx), &g_vhi[g]);
            cpa16(smem_u32(s + 3*64*AQS + sidx), &g_vlo[g]);
        }
    };

    float acc[16][4];
    #pragma unroll
    for (int ot = 0; ot < 16; ot++)
        #pragma unroll
        for (int i = 0; i < 4; i++) acc[ot][i] = 0.f;
    float m0 = -1e30f, m1 = -1e30f, l0 = 0.f, l1 = 0.f;

    int nkt = 2 * qt + 2;
    issue_kv(0, 0);
    asm volatile("cp.async.commit_group;\n" ::: "memory");

    for (int kt = 0; kt < nkt; kt++) {
        if (kt + 1 < nkt) issue_kv(kt + 1, (kt + 1) & 1);
        asm volatile("cp.async.commit_group;\n" ::: "memory");
        asm volatile("cp.async.wait_group 1;\n" ::: "memory");
        __syncthreads();

        if (kt * 64 > qt * 128 + warp * 16 + 15) {
            __syncthreads();
            continue;
        }

        __nv_bfloat16* s = sKV + (kt & 1) * KVST;
        __nv_bfloat16* sKh = s;
        __nv_bfloat16* sKl = s + 64*AQS;
        __nv_bfloat16* sVh = s + 2*64*AQS;
        __nv_bfloat16* sVl = s + 3*64*AQS;

        float sc[8][4];
        #pragma unroll
        for (int nt = 0; nt < 8; nt++)
            #pragma unroll
            for (int i = 0; i < 4; i++) sc[nt][i] = 0.f;

        #pragma unroll
        for (int kk = 0; kk < 8; kk++) {
            uint32_t ah[4], al[4];
            int qidx = (warp * 16 + (lane & 15)) * AQS + kk * 16 + ((lane >> 4) << 3);
            ldm_x4(ah, smem_u32(&sQh[qidx]));
            ldm_x4(al, smem_u32(&sQl[qidx]));
            #pragma unroll
            for (int nc = 0; nc < 4; nc++) {
                uint32_t kh4[4], kl4[4];
                int kidx = (nc * 16 + (lane & 15)) * AQS + kk * 16 + ((lane >> 4) << 3);
                ldm_x4(kh4, smem_u32(&sKh[kidx]));
                ldm_x4(kl4, smem_u32(&sKl[kidx]));
                #pragma unroll
                for (int hf = 0; hf < 2; hf++) {
                    int nt = nc * 2 + hf;
                    mma_bf16(sc[nt], ah, kh4[hf], kh4[hf + 2]);
                    mma_bf16(sc[nt], ah, kl4[hf], kl4[hf + 2]);
                    mma_bf16(sc[nt], al, kh4[hf], kh4[hf + 2]);
                }
            }
        }

        int row0 = qt * 128 + warp * 16 + (lane >> 2);
        int col0 = kt * 64 + ((lane & 3) << 1);
        float ml0 = -1e30f, ml1 = -1e30f;
        bool needmask = (kt * 64 + 63) > (qt * 128 + warp * 16);
        if (needmask) {
            #pragma unroll
            for (int nt = 0; nt < 8; nt++) {
                int c0 = col0 + nt * 8;
                float v0 = sc[nt][0] + ((c0    ) > row0     ? NEG_ : 0.f);
                float v1 = sc[nt][1] + ((c0 + 1) > row0     ? NEG_ : 0.f);
                float v2 = sc[nt][2] + ((c0    ) > row0 + 8 ? NEG_ : 0.f);
                float v3 = sc[nt][3] + ((c0 + 1) > row0 + 8 ? NEG_ : 0.f);
                sc[nt][0] = v0; sc[nt][1] = v1; sc[nt][2] = v2; sc[nt][3] = v3;
                ml0 = fmaxf(ml0, fmaxf(v0, v1));
                ml1 = fmaxf(ml1, fmaxf(v2, v3));
            }
        } else {
            #pragma unroll
            for (int nt = 0; nt < 8; nt++) {
                ml0 = fmaxf(ml0, fmaxf(sc[nt][0], sc[nt][1]));
                ml1 = fmaxf(ml1, fmaxf(sc[nt][2], sc[nt][3]));
            }
        }
        ml0 = fmaxf(ml0, __shfl_xor_sync(0xffffffffu, ml0, 1));
        ml0 = fmaxf(ml0, __shfl_xor_sync(0xffffffffu, ml0, 2));
        ml1 = fmaxf(ml1, __shfl_xor_sync(0xffffffffu, ml1, 1));
        ml1 = fmaxf(ml1, __shfl_xor_sync(0xffffffffu, ml1, 2));
        float nm0 = fmaxf(m0, ml0), nm1 = fmaxf(m1, ml1);
        float corr0 = __expf(m0 - nm0), corr1 = __expf(m1 - nm1);
        m0 = nm0; m1 = nm1;

        uint32_t ph[8][2], pl[8][2];
        float sum0 = 0.f, sum1 = 0.f;
        #pragma unroll
        for (int nt = 0; nt < 8; nt++) {
            float p0 = __expf(sc[nt][0] - nm0);
            float p1 = __expf(sc[nt][1] - nm0);
            float p2 = __expf(sc[nt][2] - nm1);
            float p3 = __expf(sc[nt][3] - nm1);
            sum0 += p0 + p1; sum1 += p2 + p3;
            __nv_bfloat162 h01 = __floats2bfloat162_rn(p0, p1);
            __nv_bfloat162 h23 = __floats2bfloat162_rn(p2, p3);
            ph[nt][0] = bf2_u32(h01);
            ph[nt][1] = bf2_u32(h23);
            __nv_bfloat162 l01 = __floats2bfloat162_rn(p0 - __bfloat162float(h01.x),
                                                       p1 - __bfloat162float(h01.y));
            __nv_bfloat162 l23 = __floats2bfloat162_rn(p2 - __bfloat162float(h23.x),
                                                       p3 - __bfloat162float(h23.y));
            pl[nt][0] = bf2_u32(l01);
            pl[nt][1] = bf2_u32(l23);
        }
        sum0 += __shfl_xor_sync(0xffffffffu, sum0, 1);
        sum0 += __shfl_xor_sync(0xffffffffu, sum0, 2);
        sum1 += __shfl_xor_sync(0xffffffffu, sum1, 1);
        sum1 += __shfl_xor_sync(0xffffffffu, sum1, 2);
        l0 = l0 * corr0 + sum0;
        l1 = l1 * corr1 + sum1;
        #pragma unroll
        for (int ot = 0; ot < 16; ot++) {
            acc[ot][0] *= corr0; acc[ot][1] *= corr0;
            acc[ot][2] *= corr1; acc[ot][3] *= corr1;
        }

        #pragma unroll
        for (int k2 = 0; k2 < 4; k2++) {
            uint32_t a0 = ph[2*k2][0], a1 = ph[2*k2][1];
            uint32_t a2 = ph[2*k2+1][0], a3 = ph[2*k2+1][1];
            uint32_t e0 = pl[2*k2][0], e1 = pl[2*k2][1];
            uint32_t e2 = pl[2*k2+1][0], e3 = pl[2*k2+1][1];
            #pragma unroll
            for (int nc = 0; nc < 8; nc++) {
                uint32_t vh4[4], vl4[4];
                int vidx = (k2 * 16 + (lane & 15)) * AQS + nc * 16 + ((lane >> 4) << 3);
                ldm_x4_t(vh4, smem_u32(&sVh[vidx]));
                ldm_x4_t(vl4, smem_u32(&sVl[vidx]));
                #pragma unroll
                for (int hf = 0; hf < 2; hf++) {
                    int ot = nc * 2 + hf, of = hf * 2;
                    mma_bf16_s(acc[ot], a0, a1, a2, a3, vh4[of], vh4[of + 1]);
                    mma_bf16_s(acc[ot], a0, a1, a2, a3, vl4[of], vl4[of + 1]);
                    mma_bf16_s(acc[ot], e0, e1, e2, e3, vh4[of], vh4[of + 1]);
                }
            }
        }
        __syncthreads();
    }

    // ---- epilogue: normalize, gate, write fp16 gated output
    float inv0 = 1.f / l0, inv1 = 1.f / l1;
    int srow = qt * 128 + warp * 16 + (lane >> 2);
    #pragma unroll
    for (int rp = 0; rp < 2; rp++) {
        int s = srow + rp * 8;
        size_t bs = (size_t)b * S_ + s;
        float inv = rp ? inv1 : inv0;
        #pragma unroll
        for (int ot = 0; ot < 16; ot++) {
            int c0 = ot * 8 + ((lane & 3) << 1);
            float2 g2 = *(const float2*)&g_qkv[bs * (size_t)NQKV + h * (2*D_) + D_ + c0];
            float o0 = acc[ot][rp*2    ] * inv * (1.f / (1.f + __expf(-g2.x)));
            float o1 = acc[ot][rp*2 + 1] * inv * (1.f / (1.f + __expf(-g2.y)));
            __half2 h2 = __floats2half2_rn(o0, o1);
            size_t oi = bs * (size_t)(H_*D_) + h * D_ + c0;
            *(uint32_t*)&g_gated[oi] = h2_u32(h2);
        }
    }
}

// ---------------- launch ----------------------------------------------------
extern "C" void kernel_launch(void* const* d_in, const int* in_sizes, int n_in,
                              void* d_out, int out_size) {
    const float* hidden = (const float*)d_in[0];
    const float* cosb   = (const float*)d_in[1];
    const float* sinb   = (const float*)d_in[2];
    // d_in[3] = attention_mask (pure causal; computed arithmetically)
    const float* wq     = (const float*)d_in[4];
    const float* wk     = (const float*)d_in[5];
    const float* wv     = (const float*)d_in[6];
    const float* wo     = (const float*)d_in[7];
    const float* qnw    = (const float*)d_in[8];
    const float* knw    = (const float*)d_in[9];
    float* out = (float*)d_out;

    float* qkv;
    cudaGetSymbolAddress((void**)&qkv, g_qkv);
    __half *hh, *wqkv, *wog, *gated;
    cudaGetSymbolAddress((void**)&hh,    g_hh);
    cudaGetSymbolAddress((void**)&wqkv,  g_wqkv);
    cudaGetSymbolAddress((void**)&wog,   g_wo);
    cudaGetSymbolAddress((void**)&gated, g_gated);

    cudaFuncSetAttribute(attn_mma_kernel,
                         cudaFuncAttributeMaxDynamicSharedMemorySize, ATT_SMEM);
    cudaFuncSetAttribute(gemm_fp16,
                         cudaFuncAttributeMaxDynamicSharedMemorySize, GSMEMF);

    const int M = B_ * S_;   // 8192

    // fp32 -> fp16 converts
    conv_kernel<<<(B_*S_*HID_)/1024, 256>>>(hidden, hh);
    conv_off_kernel<<<(HID_*H_*2*D_)/1024, 256>>>(wq, wqkv, H_*2*D_, 0);
    conv_off_kernel<<<(HID_*KV_*D_)/1024, 256>>>(wk, wqkv, KV_*D_, 4096);
    conv_off_kernel<<<(HID_*KV_*D_)/1024, 256>>>(wv, wqkv, KV_*D_, 4608);
    conv_kernel<<<(H_*D_*HID_)/1024, 256>>>(wo, wog);

    // merged QKV projection (fp16 tensor cores)
    gemm_fp16<<<dim3(NQKV/128, M/128), 256, GSMEMF>>>(hh, wqkv, qkv, M, NQKV, HID_);

    // norms + rope -> bf16 hi/lo (Q pre-scaled)
    norm_rope_kernel<<<dim3(M, 5), 128>>>(cosb, sinb, qnw, knw);

    // tensor-core attention (+ fused sigmoid gate, fp16 out)
    attn_mma_kernel<<<dim3(B_*H_, S_/128), 256, ATT_SMEM>>>();

    // output projection (fp16 tensor cores)
    gemm_fp16<<<dim3(HID_/128, M/128), 256, GSMEMF>>>(gated, wog, out, M, HID_, H_*D_);
}

// round 15
// speedup vs baseline: 1.8651x; 1.1663x over previous
#include <cuda_runtime.h>
#include <cuda_bf16.h>
#include <cuda_fp16.h>
#include <math.h>
#include <stdint.h>

#define B_ 4
#define S_ 2048
#define HID_ 2048
#define H_ 16
#define KV_ 4
#define D_ 128
#define ROT_ 32
#define NEG_ (-1000000000.0f)
#define SCALE_ 0.08838834764831845f   // D^-0.5
#define NQKV 5120                     // merged projection width

// ---------------- scratch (device globals; no allocations allowed) ----------
__device__ float g_qkv  [(size_t)B_*S_*NQKV];      // [M, 5120] q|gate|k|v
__device__ __half g_hh   [(size_t)B_*S_*HID_];     // hidden fp16
__device__ __half g_wqkv [(size_t)HID_*NQKV];      // merged W fp16 [K, 5120]
__device__ __half g_wo   [(size_t)H_*D_*HID_];     // Wo fp16 [2048, 2048]
__device__ __half g_gated[(size_t)B_*S_*H_*D_];    // gated attn fp16
__device__ __half g_qh  [(size_t)B_*H_*S_*D_];     // q fp16 hi
__device__ __half g_ql  [(size_t)B_*H_*S_*D_];     // q fp16 lo
__device__ __half g_kf  [(size_t)B_*KV_*S_*D_];    // k fp16
__device__ __half g_vf  [(size_t)B_*KV_*S_*D_];    // v fp16

// ---------------- helpers -----------------------------------------------------
__device__ __forceinline__ uint32_t smem_u32(const void* p) {
    return (uint32_t)__cvta_generic_to_shared(p);
}
__device__ __forceinline__ void ldm_x4(uint32_t* r, uint32_t addr) {
    asm volatile("ldmatrix.sync.aligned.m8n8.x4.shared.b16 {%0,%1,%2,%3}, [%4];\n"
                 : "=r"(r[0]), "=r"(r[1]), "=r"(r[2]), "=r"(r[3]) : "r"(addr));
}
__device__ __forceinline__ void ldm_x4_t(uint32_t* r, uint32_t addr) {
    asm volatile("ldmatrix.sync.aligned.m8n8.x4.trans.shared.b16 {%0,%1,%2,%3}, [%4];\n"
                 : "=r"(r[0]), "=r"(r[1]), "=r"(r[2]), "=r"(r[3]) : "r"(addr));
}
__device__ __forceinline__ void mma_f16(float* c, const uint32_t* a,
                                        uint32_t b0, uint32_t b1) {
    asm volatile(
        "mma.sync.aligned.m16n8k16.row.col.f32.f16.f16.f32 "
        "{%0,%1,%2,%3}, {%4,%5,%6,%7}, {%8,%9}, {%0,%1,%2,%3};\n"
        : "+f"(c[0]), "+f"(c[1]), "+f"(c[2]), "+f"(c[3])
        : "r"(a[0]), "r"(a[1]), "r"(a[2]), "r"(a[3]), "r"(b0), "r"(b1));
}
__device__ __forceinline__ void mma_f16_s(float* c, uint32_t a0, uint32_t a1,
                                          uint32_t a2, uint32_t a3,
                                          uint32_t b0, uint32_t b1) {
    asm volatile(
        "mma.sync.aligned.m16n8k16.row.col.f32.f16.f16.f32 "
        "{%0,%1,%2,%3}, {%4,%5,%6,%7}, {%8,%9}, {%0,%1,%2,%3};\n"
        : "+f"(c[0]), "+f"(c[1]), "+f"(c[2]), "+f"(c[3])
        : "r"(a0), "r"(a1), "r"(a2), "r"(a3), "r"(b0), "r"(b1));
}
__device__ __forceinline__ uint32_t h2_u32(__half2 v) {
    return *reinterpret_cast<uint32_t*>(&v);
}
__device__ __forceinline__ void cpa16(uint32_t dst, const void* src) {
    asm volatile("cp.async.cg.shared.global [%0], [%1], 16;\n"
                 :: "r"(dst), "l"(src));
}

// ---------------- convert fp32 -> fp16 (contiguous) ---------------------------
__global__ __launch_bounds__(256)
void conv_kernel(const float* __restrict__ src, __half* __restrict__ dst) {
    size_t i = (size_t)blockIdx.x * 256 + threadIdx.x;
    float4 v = ((const float4*)src)[i];
    __half2 h0 = __floats2half2_rn(v.x, v.y);
    __half2 h1 = __floats2half2_rn(v.z, v.w);
    ((uint2*)dst)[i] = make_uint2(h2_u32(h0), h2_u32(h1));
}

// ---------------- convert with column offset into merged weight buffer -------
__global__ __launch_bounds__(256)
void conv_off_kernel(const float* __restrict__ src, __half* __restrict__ dst,
                     int ncols, int coloff) {
    size_t i = (size_t)blockIdx.x * 256 + threadIdx.x;
    int c4 = ncols >> 2;
    int row = (int)(i / c4), col = (int)(i % c4) << 2;
    float4 v = ((const float4*)src)[i];
    __half2 h0 = __floats2half2_rn(v.x, v.y);
    __half2 h1 = __floats2half2_rn(v.z, v.w);
    size_t o = ((size_t)row * NQKV + coloff + col) >> 2;
    ((uint2*)dst)[o] = make_uint2(h2_u32(h0), h2_u32(h1));
}

// ---------------- fp16 tensor-core GEMM, 128x128x32, 256 thr, 2-stage --------
#define ASTR 40
#define BSTR 136
#define A_ELE (128*ASTR)
#define B_ELE (32*BSTR)
#define FSTG (A_ELE + B_ELE)
#define GSMEMF (2*FSTG*2)

__global__ __launch_bounds__(256)
void gemm_fp16(const __half* __restrict__ A, const __half* __restrict__ B,
               float* __restrict__ C, int M, int N, int K) {
    extern __shared__ __half fsm[];
    int tid = threadIdx.x;
    int warp = tid >> 5, lane = tid & 31;
    int wm = (warp >> 2) * 64;
    int wn = (warp & 3) * 32;

    const __half* Ab = A + (size_t)blockIdx.y * 128 * K;
    const __half* Bb = B + (size_t)blockIdx.x * 128;

    float acc[4][4][4];
    #pragma unroll
    for (int mt = 0; mt < 4; mt++)
        #pragma unroll
        for (int nt = 0; nt < 4; nt++)
            #pragma unroll
            for (int i = 0; i < 4; i++) acc[mt][nt][i] = 0.f;

    int KT = K >> 5;

    auto issue = [&](int kt, int st) {
        __half* s = fsm + st * FSTG;
        int k0 = kt << 5;
        #pragma unroll
        for (int c = tid; c < 512; c += 256) {
            int row = c >> 2, col = (c & 3) << 3;
            cpa16(smem_u32(s + row * ASTR + col), Ab + (size_t)row * K + k0 + col);
        }
        #pragma unroll
        for (int c = tid; c < 512; c += 256) {
            int row = c >> 4, col = (c & 15) << 3;
            cpa16(smem_u32(s + A_ELE + row * BSTR + col), Bb + (size_t)(k0 + row) * N + col);
        }
        asm volatile("cp.async.commit_group;\n" ::: "memory");
    };

    issue(0, 0);
    for (int kt = 0; kt < KT; kt++) {
        asm volatile("cp.async.wait_group 0;\n" ::: "memory");
        __syncthreads();
        if (kt + 1 < KT) issue(kt + 1, (kt + 1) & 1);

        __half* s = fsm + (kt & 1) * FSTG;
        __half* sA = s;
        __half* sB = s + A_ELE;

        #pragma unroll
        for (int ks = 0; ks < 2; ks++) {
            int kk = ks * 16;
            uint32_t af[4][4];
            #pragma unroll
            for (int mt = 0; mt < 4; mt++) {
                int row = wm + mt * 16 + (lane & 15);
                int col = kk + ((lane >> 4) << 3);
                ldm_x4(af[mt], smem_u32(&sA[row * ASTR + col]));
            }
            uint32_t bf[2][4];
            #pragma unroll
            for (int nc = 0; nc < 2; nc++) {
                int row = kk + (lane & 15);
                int col = wn + nc * 16 + ((lane >> 4) << 3);
                ldm_x4_t(bf[nc], smem_u32(&sB[row * BSTR + col]));
            }
            #pragma unroll
            for (int mt = 0; mt < 4; mt++) {
                #pragma unroll
                for (int nt = 0; nt < 4; nt++) {
                    int nc = nt >> 1, off = (nt & 1) << 1;
                    mma_f16(acc[mt][nt], af[mt], bf[nc][off], bf[nc][off + 1]);
                }
            }
        }
        __syncthreads();
    }

    float* Cb = C + (size_t)blockIdx.y * 128 * N + (size_t)blockIdx.x * 128;
    #pragma unroll
    for (int mt = 0; mt < 4; mt++) {
        #pragma unroll
        for (int nt = 0; nt < 4; nt++) {
            int r = wm + mt * 16 + (lane >> 2);
            int c = wn + nt * 8 + ((lane & 3) << 1);
            *(float2*)&Cb[(size_t)r * N + c] = make_float2(acc[mt][nt][0], acc[mt][nt][1]);
            *(float2*)&Cb[(size_t)(r + 8) * N + c] = make_float2(acc[mt][nt][2], acc[mt][nt][3]);
        }
    }
}

// ---------------- merged RMSNorm + RoPE, parallel over head groups ----------
// grid (M, 5): y in 0..3 -> Q heads 4y..4y+3;  y == 4 -> all KV heads.
__global__ __launch_bounds__(128)
void norm_rope_kernel(const float* __restrict__ cosb, const float* __restrict__ sinb,
                      const float* __restrict__ qw, const float* __restrict__ kw) {
    int bs = blockIdx.x, grp = blockIdx.y, d = threadIdx.x;
    float cthis = 0.f, sthis = 0.f;
    if (d < ROT_) {
        cthis = cosb[(size_t)bs * ROT_ + d];
        sthis = sinb[(size_t)bs * ROT_ + d];
    }
    int b = bs / S_, s = bs % S_;
    int warp = d >> 5, lane = d & 31;
    __shared__ float ws[4];
    const float* rowp = g_qkv + (size_t)bs * NQKV;

    if (grp < 4) {
        float qwd = 1.f + qw[d];
        #pragma unroll
        for (int hh = 0; hh < 4; hh++) {
            int h = grp * 4 + hh;
            float x = rowp[h * (2*D_) + d];
            float v = x * x;
            #pragma unroll
            for (int off = 16; off; off >>= 1) v += __shfl_xor_sync(0xffffffffu, v, off);
            if (lane == 0) ws[warp] = v;
            __syncthreads();
            float tot = ws[0] + ws[1] + ws[2] + ws[3];
            __syncthreads();

            float xn = x * rsqrtf(tot * (1.f/128.f) + 1e-6f) * qwd;
            float o = xn;
            if (d < ROT_) {
                float xp = __shfl_xor_sync(0xffffffffu, xn, 16);
                float rot = (d < 16) ? -xp : xp;
                o = xn * cthis + rot * sthis;
            }
            o *= SCALE_;
            size_t idx = (((size_t)b * H_ + h) * S_ + s) * D_ + d;
            __half hi = __float2half(o);
            g_qh[idx] = hi;
            g_ql[idx] = __float2half(o - __half2float(hi));
        }
    } else {
        float kwd = 1.f + kw[d];
        #pragma unroll
        for (int kv = 0; kv < KV_; kv++) {
            float x = rowp[4096 + kv * D_ + d];
            float v = x * x;
            #pragma unroll
            for (int off = 16; off; off >>= 1) v += __shfl_xor_sync(0xffffffffu, v, off);
            if (lane == 0) ws[warp] = v;
            __syncthreads();
            float tot = ws[0] + ws[1] + ws[2] + ws[3];
            __syncthreads();

            float xn = x * rsqrtf(tot * (1.f/128.f) + 1e-6f) * kwd;
            float o = xn;
            if (d < ROT_) {
                float xp = __shfl_xor_sync(0xffffffffu, xn, 16);
                float rot = (d < 16) ? -xp : xp;
                o = xn * cthis + rot * sthis;
            }
            size_t oidx = (((size_t)b * KV_ + kv) * S_ + s) * D_ + d;
            g_kf[oidx] = __float2half(o);
            g_vf[oidx] = __float2half(rowp[4608 + kv * D_ + d]);
        }
    }
}

// ---------------- fp16 flash attention, cp.async double-buffered K/V --------
// QK: q hi/lo x k single (2 mmas); PV: p hi/lo x v single (2 mmas).
#define AQS 136
#define KVST (2*64*AQS)                     // K + V per stage (fp16 elems)
#define ATT_SMEM ((2*128*AQS + 2*KVST) * 2) // bytes

__global__ __launch_bounds__(256)
void attn_mma_kernel() {
    extern __shared__ __align__(16) __half smA[];
    __half* sQh = smA;
    __half* sQl = sQh + 128 * AQS;
    __half* sKV = sQl + 128 * AQS;   // 2 stages x [K|V]

    int tid = threadIdx.x, warp = tid >> 5, lane = tid & 31;
    int bh = blockIdx.x;
    int qt = (int)gridDim.y - 1 - (int)blockIdx.y;   // LPT
    int b = bh >> 4, h = bh & 15, kvh = h >> 2;

    size_t qoff = ((size_t)bh * S_ + (size_t)qt * 128) * D_;
    size_t kvoff = ((size_t)(b * KV_ + kvh) * S_) * D_;

    for (int i = tid; i < 2048; i += 256) {
        int r = i >> 4, c = (i & 15) << 3;
        *(uint4*)&sQh[r * AQS + c] = *(const uint4*)&g_qh[qoff + (size_t)r * D_ + c];
        *(uint4*)&sQl[r * AQS + c] = *(const uint4*)&g_ql[qoff + (size_t)r * D_ + c];
    }

    auto issue_kv = [&](int kt, int st) {
        __half* s = sKV + st * KVST;
        size_t koff = kvoff + (size_t)kt * 64 * D_;
        #pragma unroll
        for (int i = tid; i < 1024; i += 256) {
            int r = i >> 4, c = (i & 15) << 3;
            size_t g = koff + (size_t)r * D_ + c;
            int sidx = r * AQS + c;
            cpa16(smem_u32(s + sidx), &g_kf[g]);
            cpa16(smem_u32(s + 64*AQS + sidx), &g_vf[g]);
        }
    };

    float acc[16][4];
    #pragma unroll
    for (int ot = 0; ot < 16; ot++)
        #pragma unroll
        for (int i = 0; i < 4; i++) acc[ot][i] = 0.f;
    float m0 = -1e30f, m1 = -1e30f, l0 = 0.f, l1 = 0.f;

    int nkt = 2 * qt + 2;
    issue_kv(0, 0);
    asm volatile("cp.async.commit_group;\n" ::: "memory");

    for (int kt = 0; kt < nkt; kt++) {
        if (kt + 1 < nkt) issue_kv(kt + 1, (kt + 1) & 1);
        asm volatile("cp.async.commit_group;\n" ::: "memory");
        asm volatile("cp.async.wait_group 1;\n" ::: "memory");
        __syncthreads();

        if (kt * 64 > qt * 128 + warp * 16 + 15) {
            __syncthreads();
            continue;
        }

        __half* s = sKV + (kt & 1) * KVST;
        __half* sK = s;
        __half* sV = s + 64*AQS;

        float sc[8][4];
        #pragma unroll
        for (int nt = 0; nt < 8; nt++)
            #pragma unroll
            for (int i = 0; i < 4; i++) sc[nt][i] = 0.f;

        #pragma unroll
        for (int kk = 0; kk < 8; kk++) {
            uint32_t ah[4], al[4];
            int qidx = (warp * 16 + (lane & 15)) * AQS + kk * 16 + ((lane >> 4) << 3);
            ldm_x4(ah, smem_u32(&sQh[qidx]));
            ldm_x4(al, smem_u32(&sQl[qidx]));
            #pragma unroll
            for (int nc = 0; nc < 4; nc++) {
                uint32_t k4[4];
                int kidx = (nc * 16 + (lane & 15)) * AQS + kk * 16 + ((lane >> 4) << 3);
                ldm_x4(k4, smem_u32(&sK[kidx]));
                #pragma unroll
                for (int hf = 0; hf < 2; hf++) {
                    int nt = nc * 2 + hf;
                    mma_f16(sc[nt], ah, k4[hf], k4[hf + 2]);
                    mma_f16(sc[nt], al, k4[hf], k4[hf + 2]);
                }
            }
        }

        int row0 = qt * 128 + warp * 16 + (lane >> 2);
        int col0 = kt * 64 + ((lane & 3) << 1);
        float ml0 = -1e30f, ml1 = -1e30f;
        bool needmask = (kt * 64 + 63) > (qt * 128 + warp * 16);
        if (needmask) {
            #pragma unroll
            for (int nt = 0; nt < 8; nt++) {
                int c0 = col0 + nt * 8;
                float v0 = sc[nt][0] + ((c0    ) > row0     ? NEG_ : 0.f);
                float v1 = sc[nt][1] + ((c0 + 1) > row0     ? NEG_ : 0.f);
                float v2 = sc[nt][2] + ((c0    ) > row0 + 8 ? NEG_ : 0.f);
                float v3 = sc[nt][3] + ((c0 + 1) > row0 + 8 ? NEG_ : 0.f);
                sc[nt][0] = v0; sc[nt][1] = v1; sc[nt][2] = v2; sc[nt][3] = v3;
                ml0 = fmaxf(ml0, fmaxf(v0, v1));
                ml1 = fmaxf(ml1, fmaxf(v2, v3));
            }
        } else {
            #pragma unroll
            for (int nt = 0; nt < 8; nt++) {
                ml0 = fmaxf(ml0, fmaxf(sc[nt][0], sc[nt][1]));
                ml1 = fmaxf(ml1, fmaxf(sc[nt][2], sc[nt][3]));
            }
        }
        ml0 = fmaxf(ml0, __shfl_xor_sync(0xffffffffu, ml0, 1));
        ml0 = fmaxf(ml0, __shfl_xor_sync(0xffffffffu, ml0, 2));
        ml1 = fmaxf(ml1, __shfl_xor_sync(0xffffffffu, ml1, 1));
        ml1 = fmaxf(ml1, __shfl_xor_sync(0xffffffffu, ml1, 2));
        float nm0 = fmaxf(m0, ml0), nm1 = fmaxf(m1, ml1);
        float corr0 = __expf(m0 - nm0), corr1 = __expf(m1 - nm1);
        m0 = nm0; m1 = nm1;

        uint32_t ph[8][2], pl[8][2];
        float sum0 = 0.f, sum1 = 0.f;
        #pragma unroll
        for (int nt = 0; nt < 8; nt++) {
            float p0 = __expf(sc[nt][0] - nm0);
            float p1 = __expf(sc[nt][1] - nm0);
            float p2 = __expf(sc[nt][2] - nm1);
            float p3 = __expf(sc[nt][3] - nm1);
            sum0 += p0 + p1; sum1 += p2 + p3;
            __half2 h01 = __floats2half2_rn(p0, p1);
            __half2 h23 = __floats2half2_rn(p2, p3);
            ph[nt][0] = h2_u32(h01);
            ph[nt][1] = h2_u32(h23);
            __half2 l01 = __floats2half2_rn(p0 - __half2float(h01.x),
                                            p1 - __half2float(h01.y));
            __half2 l23 = __floats2half2_rn(p2 - __half2float(h23.x),
                                            p3 - __half2float(h23.y));
            pl[nt][0] = h2_u32(l01);
            pl[nt][1] = h2_u32(l23);
        }
        sum0 += __shfl_xor_sync(0xffffffffu, sum0, 1);
        sum0 += __shfl_xor_sync(0xffffffffu, sum0, 2);
        sum1 += __shfl_xor_sync(0xffffffffu, sum1, 1);
        sum1 += __shfl_xor_sync(0xffffffffu, sum1, 2);
        l0 = l0 * corr0 + sum0;
        l1 = l1 * corr1 + sum1;
        #pragma unroll
        for (int ot = 0; ot < 16; ot++) {
            acc[ot][0] *= corr0; acc[ot][1] *= corr0;
            acc[ot][2] *= corr1; acc[ot][3] *= corr1;
        }

        #pragma unroll
        for (int k2 = 0; k2 < 4; k2++) {
            uint32_t a0 = ph[2*k2][0], a1 = ph[2*k2][1];
            uint32_t a2 = ph[2*k2+1][0], a3 = ph[2*k2+1][1];
            uint32_t e0 = pl[2*k2][0], e1 = pl[2*k2][1];
            uint32_t e2 = pl[2*k2+1][0], e3 = pl[2*k2+1][1];
            #pragma unroll
            for (int nc = 0; nc < 8; nc++) {
                uint32_t v4[4];
                int vidx = (k2 * 16 + (lane & 15)) * AQS + nc * 16 + ((lane >> 4) << 3);
                ldm_x4_t(v4, smem_u32(&sV[vidx]));
                #pragma unroll
                for (int hf = 0; hf < 2; hf++) {
                    int ot = nc * 2 + hf, of = hf * 2;
                    mma_f16_s(acc[ot], a0, a1, a2, a3, v4[of], v4[of + 1]);
                    mma_f16_s(acc[ot], e0, e1, e2, e3, v4[of], v4[of + 1]);
                }
            }
        }
        __syncthreads();
    }

    // ---- epilogue: normalize, gate, write fp16 gated output
    float inv0 = 1.f / l0, inv1 = 1.f / l1;
    int srow = qt * 128 + warp * 16 + (lane >> 2);
    #pragma unroll
    for (int rp = 0; rp < 2; rp++) {
        int s = srow + rp * 8;
        size_t bs = (size_t)b * S_ + s;
        float inv = rp ? inv1 : inv0;
        #pragma unroll
        for (int ot = 0; ot < 16; ot++) {
            int c0 = ot * 8 + ((lane & 3) << 1);
            float2 g2 = *(const float2*)&g_qkv[bs * (size_t)NQKV + h * (2*D_) + D_ + c0];
            float o0 = acc[ot][rp*2    ] * inv * (1.f / (1.f + __expf(-g2.x)));
            float o1 = acc[ot][rp*2 + 1] * inv * (1.f / (1.f + __expf(-g2.y)));
            __half2 h2 = __floats2half2_rn(o0, o1);
            size_t oi = bs * (size_t)(H_*D_) + h * D_ + c0;
            *(uint32_t*)&g_gated[oi] = h2_u32(h2);
        }
    }
}

// ---------------- launch ----------------------------------------------------
extern "C" void kernel_launch(void* const* d_in, const int* in_sizes, int n_in,
                              void* d_out, int out_size) {
    const float* hidden = (const float*)d_in[0];
    const float* cosb   = (const float*)d_in[1];
    const float* sinb   = (const float*)d_in[2];
    // d_in[3] = attention_mask (pure causal; computed arithmetically)
    const float* wq     = (const float*)d_in[4];
    const float* wk     = (const float*)d_in[5];
    const float* wv     = (const float*)d_in[6];
    const float* wo     = (const float*)d_in[7];
    const float* qnw    = (const float*)d_in[8];
    const float* knw    = (const float*)d_in[9];
    float* out = (float*)d_out;

    float* qkv;
    cudaGetSymbolAddress((void**)&qkv, g_qkv);
    __half *hh, *wqkv, *wog, *gated;
    cudaGetSymbolAddress((void**)&hh,    g_hh);
    cudaGetSymbolAddress((void**)&wqkv,  g_wqkv);
    cudaGetSymbolAddress((void**)&wog,   g_wo);
    cudaGetSymbolAddress((void**)&gated, g_gated);

    cudaFuncSetAttribute(attn_mma_kernel,
                         cudaFuncAttributeMaxDynamicSharedMemorySize, ATT_SMEM);
    cudaFuncSetAttribute(gemm_fp16,
                         cudaFuncAttributeMaxDynamicSharedMemorySize, GSMEMF);

    const int M = B_ * S_;   // 8192

    // fp32 -> fp16 converts
    conv_kernel<<<(B_*S_*HID_)/1024, 256>>>(hidden, hh);
    conv_off_kernel<<<(HID_*H_*2*D_)/1024, 256>>>(wq, wqkv, H_*2*D_, 0);
    conv_off_kernel<<<(HID_*KV_*D_)/1024, 256>>>(wk, wqkv, KV_*D_, 4096);
    conv_off_kernel<<<(HID_*KV_*D_)/1024, 256>>>(wv, wqkv, KV_*D_, 4608);
    conv_kernel<<<(H_*D_*HID_)/1024, 256>>>(wo, wog);

    // merged QKV projection (fp16 tensor cores)
    gemm_fp16<<<dim3(NQKV/128, M/128), 256, GSMEMF>>>(hh, wqkv, qkv, M, NQKV, HID_);

    // norms + rope -> fp16 (Q pre-scaled, hi/lo; K,V single)
    norm_rope_kernel<<<dim3(M, 5), 128>>>(cosb, sinb, qnw, knw);

    // fp16 attention (+ fused sigmoid gate)
    attn_mma_kernel<<<dim3(B_*H_, S_/128), 256, ATT_SMEM>>>();

    // output projection (fp16 tensor cores)
    gemm_fp16<<<dim3(HID_/128, M/128), 256, GSMEMF>>>(gated, wog, out, M, HID_, H_*D_);
}

// round 16
// speedup vs baseline: 1.9341x; 1.0370x over previous
#include <cuda_runtime.h>
#include <cuda_bf16.h>
#include <cuda_fp16.h>
#include <math.h>
#include <stdint.h>

#define B_ 4
#define S_ 2048
#define HID_ 2048
#define H_ 16
#define KV_ 4
#define D_ 128
#define ROT_ 32
#define NEG_ (-1000000000.0f)
#define SCALE_ 0.08838834764831845f   // D^-0.5
#define NQKV 5120                     // merged projection width

// ---------------- scratch (device globals; no allocations allowed) ----------
__device__ float g_qkv  [(size_t)B_*S_*NQKV];      // [M, 5120] q|gate|k|v
__device__ __half g_hh   [(size_t)B_*S_*HID_];     // hidden fp16
__device__ __half g_wqkv [(size_t)HID_*NQKV];      // merged W fp16 [K, 5120]
__device__ __half g_wo   [(size_t)H_*D_*HID_];     // Wo fp16 [2048, 2048]
__device__ __half g_gated[(size_t)B_*S_*H_*D_];    // gated attn fp16
__device__ __half g_qh  [(size_t)B_*H_*S_*D_];     // q fp16 hi
__device__ __half g_ql  [(size_t)B_*H_*S_*D_];     // q fp16 lo
__device__ __half g_kf  [(size_t)B_*KV_*S_*D_];    // k fp16
__device__ __half g_vf  [(size_t)B_*KV_*S_*D_];    // v fp16

// ---------------- helpers -----------------------------------------------------
__device__ __forceinline__ uint32_t smem_u32(const void* p) {
    return (uint32_t)__cvta_generic_to_shared(p);
}
__device__ __forceinline__ void ldm_x4(uint32_t* r, uint32_t addr) {
    asm volatile("ldmatrix.sync.aligned.m8n8.x4.shared.b16 {%0,%1,%2,%3}, [%4];\n"
                 : "=r"(r[0]), "=r"(r[1]), "=r"(r[2]), "=r"(r[3]) : "r"(addr));
}
__device__ __forceinline__ void ldm_x4_t(uint32_t* r, uint32_t addr) {
    asm volatile("ldmatrix.sync.aligned.m8n8.x4.trans.shared.b16 {%0,%1,%2,%3}, [%4];\n"
                 : "=r"(r[0]), "=r"(r[1]), "=r"(r[2]), "=r"(r[3]) : "r"(addr));
}
__device__ __forceinline__ void mma_f16(float* c, const uint32_t* a,
                                        uint32_t b0, uint32_t b1) {
    asm volatile(
        "mma.sync.aligned.m16n8k16.row.col.f32.f16.f16.f32 "
        "{%0,%1,%2,%3}, {%4,%5,%6,%7}, {%8,%9}, {%0,%1,%2,%3};\n"
        : "+f"(c[0]), "+f"(c[1]), "+f"(c[2]), "+f"(c[3])
        : "r"(a[0]), "r"(a[1]), "r"(a[2]), "r"(a[3]), "r"(b0), "r"(b1));
}
__device__ __forceinline__ void mma_f16_s(float* c, uint32_t a0, uint32_t a1,
                                          uint32_t a2, uint32_t a3,
                                          uint32_t b0, uint32_t b1) {
    asm volatile(
        "mma.sync.aligned.m16n8k16.row.col.f32.f16.f16.f32 "
        "{%0,%1,%2,%3}, {%4,%5,%6,%7}, {%8,%9}, {%0,%1,%2,%3};\n"
        : "+f"(c[0]), "+f"(c[1]), "+f"(c[2]), "+f"(c[3])
        : "r"(a0), "r"(a1), "r"(a2), "r"(a3), "r"(b0), "r"(b1));
}
__device__ __forceinline__ uint32_t h2_u32(__half2 v) {
    return *reinterpret_cast<uint32_t*>(&v);
}
__device__ __forceinline__ void cpa16(uint32_t dst, const void* src) {
    asm volatile("cp.async.cg.shared.global [%0], [%1], 16;\n"
                 :: "r"(dst), "l"(src));
}

// ---------------- convert fp32 -> fp16 (contiguous) ---------------------------
__global__ __launch_bounds__(256)
void conv_kernel(const float* __restrict__ src, __half* __restrict__ dst) {
    size_t i = (size_t)blockIdx.x * 256 + threadIdx.x;
    float4 v = ((const float4*)src)[i];
    __half2 h0 = __floats2half2_rn(v.x, v.y);
    __half2 h1 = __floats2half2_rn(v.z, v.w);
    ((uint2*)dst)[i] = make_uint2(h2_u32(h0), h2_u32(h1));
}

// ---------------- convert with column offset into merged weight buffer -------
__global__ __launch_bounds__(256)
void conv_off_kernel(const float* __restrict__ src, __half* __restrict__ dst,
                     int ncols, int coloff) {
    size_t i = (size_t)blockIdx.x * 256 + threadIdx.x;
    int c4 = ncols >> 2;
    int row = (int)(i / c4), col = (int)(i % c4) << 2;
    float4 v = ((const float4*)src)[i];
    __half2 h0 = __floats2half2_rn(v.x, v.y);
    __half2 h1 = __floats2half2_rn(v.z, v.w);
    size_t o = ((size_t)row * NQKV + coloff + col) >> 2;
    ((uint2*)dst)[o] = make_uint2(h2_u32(h0), h2_u32(h1));
}

// ---------------- fp16 tensor-core GEMM, 128x128x32, 256 thr, 2-stage --------
#define ASTR 40
#define BSTR 136
#define A_ELE (128*ASTR)
#define B_ELE (32*BSTR)
#define FSTG (A_ELE + B_ELE)
#define GSMEMF (2*FSTG*2)

__global__ __launch_bounds__(256)
void gemm_fp16(const __half* __restrict__ A, const __half* __restrict__ B,
               float* __restrict__ C, int M, int N, int K) {
    extern __shared__ __half fsm[];
    int tid = threadIdx.x;
    int warp = tid >> 5, lane = tid & 31;
    int wm = (warp >> 2) * 64;
    int wn = (warp & 3) * 32;

    const __half* Ab = A + (size_t)blockIdx.y * 128 * K;
    const __half* Bb = B + (size_t)blockIdx.x * 128;

    float acc[4][4][4];
    #pragma unroll
    for (int mt = 0; mt < 4; mt++)
        #pragma unroll
        for (int nt = 0; nt < 4; nt++)
            #pragma unroll
            for (int i = 0; i < 4; i++) acc[mt][nt][i] = 0.f;

    int KT = K >> 5;

    auto issue = [&](int kt, int st) {
        __half* s = fsm + st * FSTG;
        int k0 = kt << 5;
        #pragma unroll
        for (int c = tid; c < 512; c += 256) {
            int row = c >> 2, col = (c & 3) << 3;
            cpa16(smem_u32(s + row * ASTR + col), Ab + (size_t)row * K + k0 + col);
        }
        #pragma unroll
        for (int c = tid; c < 512; c += 256) {
            int row = c >> 4, col = (c & 15) << 3;
            cpa16(smem_u32(s + A_ELE + row * BSTR + col), Bb + (size_t)(k0 + row) * N + col);
        }
        asm volatile("cp.async.commit_group;\n" ::: "memory");
    };

    issue(0, 0);
    for (int kt = 0; kt < KT; kt++) {
        asm volatile("cp.async.wait_group 0;\n" ::: "memory");
        __syncthreads();
        if (kt + 1 < KT) issue(kt + 1, (kt + 1) & 1);

        __half* s = fsm + (kt & 1) * FSTG;
        __half* sA = s;
        __half* sB = s + A_ELE;

        #pragma unroll
        for (int ks = 0; ks < 2; ks++) {
            int kk = ks * 16;
            uint32_t af[4][4];
            #pragma unroll
            for (int mt = 0; mt < 4; mt++) {
                int row = wm + mt * 16 + (lane & 15);
                int col = kk + ((lane >> 4) << 3);
                ldm_x4(af[mt], smem_u32(&sA[row * ASTR + col]));
            }
            uint32_t bf[2][4];
            #pragma unroll
            for (int nc = 0; nc < 2; nc++) {
                int row = kk + (lane & 15);
                int col = wn + nc * 16 + ((lane >> 4) << 3);
                ldm_x4_t(bf[nc], smem_u32(&sB[row * BSTR + col]));
            }
            #pragma unroll
            for (int mt = 0; mt < 4; mt++) {
                #pragma unroll
                for (int nt = 0; nt < 4; nt++) {
                    int nc = nt >> 1, off = (nt & 1) << 1;
                    mma_f16(acc[mt][nt], af[mt], bf[nc][off], bf[nc][off + 1]);
                }
            }
        }
        __syncthreads();
    }

    float* Cb = C + (size_t)blockIdx.y * 128 * N + (size_t)blockIdx.x * 128;
    #pragma unroll
    for (int mt = 0; mt < 4; mt++) {
        #pragma unroll
        for (int nt = 0; nt < 4; nt++) {
            int r = wm + mt * 16 + (lane >> 2);
            int c = wn + nt * 8 + ((lane & 3) << 1);
            *(float2*)&Cb[(size_t)r * N + c] = make_float2(acc[mt][nt][0], acc[mt][nt][1]);
            *(float2*)&Cb[(size_t)(r + 8) * N + c] = make_float2(acc[mt][nt][2], acc[mt][nt][3]);
        }
    }
}

// ---------------- merged RMSNorm + RoPE, parallel over head groups ----------
__global__ __launch_bounds__(128)
void norm_rope_kernel(const float* __restrict__ cosb, const float* __restrict__ sinb,
                      const float* __restrict__ qw, const float* __restrict__ kw) {
    int bs = blockIdx.x, grp = blockIdx.y, d = threadIdx.x;
    float cthis = 0.f, sthis = 0.f;
    if (d < ROT_) {
        cthis = cosb[(size_t)bs * ROT_ + d];
        sthis = sinb[(size_t)bs * ROT_ + d];
    }
    int b = bs / S_, s = bs % S_;
    int warp = d >> 5, lane = d & 31;
    __shared__ float ws[4];
    const float* rowp = g_qkv + (size_t)bs * NQKV;

    if (grp < 4) {
        float qwd = 1.f + qw[d];
        #pragma unroll
        for (int hh = 0; hh < 4; hh++) {
            int h = grp * 4 + hh;
            float x = rowp[h * (2*D_) + d];
            float v = x * x;
            #pragma unroll
            for (int off = 16; off; off >>= 1) v += __shfl_xor_sync(0xffffffffu, v, off);
            if (lane == 0) ws[warp] = v;
            __syncthreads();
            float tot = ws[0] + ws[1] + ws[2] + ws[3];
            __syncthreads();

            float xn = x * rsqrtf(tot * (1.f/128.f) + 1e-6f) * qwd;
            float o = xn;
            if (d < ROT_) {
                float xp = __shfl_xor_sync(0xffffffffu, xn, 16);
                float rot = (d < 16) ? -xp : xp;
                o = xn * cthis + rot * sthis;
            }
            o *= SCALE_;
            size_t idx = (((size_t)b * H_ + h) * S_ + s) * D_ + d;
            __half hi = __float2half(o);
            g_qh[idx] = hi;
            g_ql[idx] = __float2half(o - __half2float(hi));
        }
    } else {
        float kwd = 1.f + kw[d];
        #pragma unroll
        for (int kv = 0; kv < KV_; kv++) {
            float x = rowp[4096 + kv * D_ + d];
            float v = x * x;
            #pragma unroll
            for (int off = 16; off; off >>= 1) v += __shfl_xor_sync(0xffffffffu, v, off);
            if (lane == 0) ws[warp] = v;
            __syncthreads();
            float tot = ws[0] + ws[1] + ws[2] + ws[3];
            __syncthreads();

            float xn = x * rsqrtf(tot * (1.f/128.f) + 1e-6f) * kwd;
            float o = xn;
            if (d < ROT_) {
                float xp = __shfl_xor_sync(0xffffffffu, xn, 16);
                float rot = (d < 16) ? -xp : xp;
                o = xn * cthis + rot * sthis;
            }
            size_t oidx = (((size_t)b * KV_ + kv) * S_ + s) * D_ + d;
            g_kf[oidx] = __float2half(o);
            g_vf[oidx] = __float2half(rowp[4608 + kv * D_ + d]);
        }
    }
}

// ---------------- fp16 flash attention, cp.async double-buffered K/V --------
// QK: q hi/lo x k single (2 mmas); PV: p single x v single (1 mma).
#define AQS 136
#define KVST (2*64*AQS)                     // K + V per stage (fp16 elems)
#define ATT_SMEM ((2*128*AQS + 2*KVST) * 2) // bytes

__global__ __launch_bounds__(256)
void attn_mma_kernel() {
    extern __shared__ __align__(16) __half smA[];
    __half* sQh = smA;
    __half* sQl = sQh + 128 * AQS;
    __half* sKV = sQl + 128 * AQS;   // 2 stages x [K|V]

    int tid = threadIdx.x, warp = tid >> 5, lane = tid & 31;
    int bh = blockIdx.x;
    int qt = (int)gridDim.y - 1 - (int)blockIdx.y;   // LPT
    int b = bh >> 4, h = bh & 15, kvh = h >> 2;

    size_t qoff = ((size_t)bh * S_ + (size_t)qt * 128) * D_;
    size_t kvoff = ((size_t)(b * KV_ + kvh) * S_) * D_;

    for (int i = tid; i < 2048; i += 256) {
        int r = i >> 4, c = (i & 15) << 3;
        *(uint4*)&sQh[r * AQS + c] = *(const uint4*)&g_qh[qoff + (size_t)r * D_ + c];
        *(uint4*)&sQl[r * AQS + c] = *(const uint4*)&g_ql[qoff + (size_t)r * D_ + c];
    }

    auto issue_kv = [&](int kt, int st) {
        __half* s = sKV + st * KVST;
        size_t koff = kvoff + (size_t)kt * 64 * D_;
        #pragma unroll
        for (int i = tid; i < 1024; i += 256) {
            int r = i >> 4, c = (i & 15) << 3;
            size_t g = koff + (size_t)r * D_ + c;
            int sidx = r * AQS + c;
            cpa16(smem_u32(s + sidx), &g_kf[g]);
            cpa16(smem_u32(s + 64*AQS + sidx), &g_vf[g]);
        }
    };

    float acc[16][4];
    #pragma unroll
    for (int ot = 0; ot < 16; ot++)
        #pragma unroll
        for (int i = 0; i < 4; i++) acc[ot][i] = 0.f;
    float m0 = -1e30f, m1 = -1e30f, l0 = 0.f, l1 = 0.f;

    int nkt = 2 * qt + 2;
    issue_kv(0, 0);
    asm volatile("cp.async.commit_group;\n" ::: "memory");

    for (int kt = 0; kt < nkt; kt++) {
        if (kt + 1 < nkt) issue_kv(kt + 1, (kt + 1) & 1);
        asm volatile("cp.async.commit_group;\n" ::: "memory");
        asm volatile("cp.async.wait_group 1;\n" ::: "memory");
        __syncthreads();

        if (kt * 64 > qt * 128 + warp * 16 + 15) {
            __syncthreads();
            continue;
        }

        __half* s = sKV + (kt & 1) * KVST;
        __half* sK = s;
        __half* sV = s + 64*AQS;

        float sc[8][4];
        #pragma unroll
        for (int nt = 0; nt < 8; nt++)
            #pragma unroll
            for (int i = 0; i < 4; i++) sc[nt][i] = 0.f;

        #pragma unroll
        for (int kk = 0; kk < 8; kk++) {
            uint32_t ah[4], al[4];
            int qidx = (warp * 16 + (lane & 15)) * AQS + kk * 16 + ((lane >> 4) << 3);
            ldm_x4(ah, smem_u32(&sQh[qidx]));
            ldm_x4(al, smem_u32(&sQl[qidx]));
            #pragma unroll
            for (int nc = 0; nc < 4; nc++) {
                uint32_t k4[4];
                int kidx = (nc * 16 + (lane & 15)) * AQS + kk * 16 + ((lane >> 4) << 3);
                ldm_x4(k4, smem_u32(&sK[kidx]));
                #pragma unroll
                for (int hf = 0; hf < 2; hf++) {
                    int nt = nc * 2 + hf;
                    mma_f16(sc[nt], ah, k4[hf], k4[hf + 2]);
                    mma_f16(sc[nt], al, k4[hf], k4[hf + 2]);
                }
            }
        }

        int row0 = qt * 128 + warp * 16 + (lane >> 2);
        int col0 = kt * 64 + ((lane & 3) << 1);
        float ml0 = -1e30f, ml1 = -1e30f;
        bool needmask = (kt * 64 + 63) > (qt * 128 + warp * 16);
        if (needmask) {
            #pragma unroll
            for (int nt = 0; nt < 8; nt++) {
                int c0 = col0 + nt * 8;
                float v0 = sc[nt][0] + ((c0    ) > row0     ? NEG_ : 0.f);
                float v1 = sc[nt][1] + ((c0 + 1) > row0     ? NEG_ : 0.f);
                float v2 = sc[nt][2] + ((c0    ) > row0 + 8 ? NEG_ : 0.f);
                float v3 = sc[nt][3] + ((c0 + 1) > row0 + 8 ? NEG_ : 0.f);
                sc[nt][0] = v0; sc[nt][1] = v1; sc[nt][2] = v2; sc[nt][3] = v3;
                ml0 = fmaxf(ml0, fmaxf(v0, v1));
                ml1 = fmaxf(ml1, fmaxf(v2, v3));
            }
        } else {
            #pragma unroll
            for (int nt = 0; nt < 8; nt++) {
                ml0 = fmaxf(ml0, fmaxf(sc[nt][0], sc[nt][1]));
                ml1 = fmaxf(ml1, fmaxf(sc[nt][2], sc[nt][3]));
            }
        }
        ml0 = fmaxf(ml0, __shfl_xor_sync(0xffffffffu, ml0, 1));
        ml0 = fmaxf(ml0, __shfl_xor_sync(0xffffffffu, ml0, 2));
        ml1 = fmaxf(ml1, __shfl_xor_sync(0xffffffffu, ml1, 1));
        ml1 = fmaxf(ml1, __shfl_xor_sync(0xffffffffu, ml1, 2));
        float nm0 = fmaxf(m0, ml0), nm1 = fmaxf(m1, ml1);
        bool rescale = (nm0 != m0) || (nm1 != m1);
        float corr0 = __expf(m0 - nm0), corr1 = __expf(m1 - nm1);
        m0 = nm0; m1 = nm1;

        uint32_t ph[8][2];
        float sum0 = 0.f, sum1 = 0.f;
        #pragma unroll
        for (int nt = 0; nt < 8; nt++) {
            float p0 = __expf(sc[nt][0] - nm0);
            float p1 = __expf(sc[nt][1] - nm0);
            float p2 = __expf(sc[nt][2] - nm1);
            float p3 = __expf(sc[nt][3] - nm1);
            sum0 += p0 + p1; sum1 += p2 + p3;
            ph[nt][0] = h2_u32(__floats2half2_rn(p0, p1));
            ph[nt][1] = h2_u32(__floats2half2_rn(p2, p3));
        }
        sum0 += __shfl_xor_sync(0xffffffffu, sum0, 1);
        sum0 += __shfl_xor_sync(0xffffffffu, sum0, 2);
        sum1 += __shfl_xor_sync(0xffffffffu, sum1, 1);
        sum1 += __shfl_xor_sync(0xffffffffu, sum1, 2);
        l0 = l0 * corr0 + sum0;
        l1 = l1 * corr1 + sum1;
        if (rescale) {   // corr==1 exactly when max unchanged -> skip is exact
            #pragma unroll
            for (int ot = 0; ot < 16; ot++) {
                acc[ot][0] *= corr0; acc[ot][1] *= corr0;
                acc[ot][2] *= corr1; acc[ot][3] *= corr1;
            }
        }

        #pragma unroll
        for (int k2 = 0; k2 < 4; k2++) {
            uint32_t a0 = ph[2*k2][0], a1 = ph[2*k2][1];
            uint32_t a2 = ph[2*k2+1][0], a3 = ph[2*k2+1][1];
            #pragma unroll
            for (int nc = 0; nc < 8; nc++) {
                uint32_t v4[4];
                int vidx = (k2 * 16 + (lane & 15)) * AQS + nc * 16 + ((lane >> 4) << 3);
                ldm_x4_t(v4, smem_u32(&sV[vidx]));
                #pragma unroll
                for (int hf = 0; hf < 2; hf++) {
                    int ot = nc * 2 + hf, of = hf * 2;
                    mma_f16_s(acc[ot], a0, a1, a2, a3, v4[of], v4[of + 1]);
                }
            }
        }
        __syncthreads();
    }

    // ---- epilogue: normalize, gate, write fp16 gated output
    float inv0 = 1.f / l0, inv1 = 1.f / l1;
    int srow = qt * 128 + warp * 16 + (lane >> 2);
    #pragma unroll
    for (int rp = 0; rp < 2; rp++) {
        int s = srow + rp * 8;
        size_t bs = (size_t)b * S_ + s;
        float inv = rp ? inv1 : inv0;
        #pragma unroll
        for (int ot = 0; ot < 16; ot++) {
            int c0 = ot * 8 + ((lane & 3) << 1);
            float2 g2 = *(const float2*)&g_qkv[bs * (size_t)NQKV + h * (2*D_) + D_ + c0];
            float o0 = acc[ot][rp*2    ] * inv * (1.f / (1.f + __expf(-g2.x)));
            float o1 = acc[ot][rp*2 + 1] * inv * (1.f / (1.f + __expf(-g2.y)));
            __half2 h2 = __floats2half2_rn(o0, o1);
            size_t oi = bs * (size_t)(H_*D_) + h * D_ + c0;
            *(uint32_t*)&g_gated[oi] = h2_u32(h2);
        }
    }
}

// ---------------- launch ----------------------------------------------------
extern "C" void kernel_launch(void* const* d_in, const int* in_sizes, int n_in,
                              void* d_out, int out_size) {
    const float* hidden = (const float*)d_in[0];
    const float* cosb   = (const float*)d_in[1];
    const float* sinb   = (const float*)d_in[2];
    // d_in[3] = attention_mask (pure causal; computed arithmetically)
    const float* wq     = (const float*)d_in[4];
    const float* wk     = (const float*)d_in[5];
    const float* wv     = (const float*)d_in[6];
    const float* wo     = (const float*)d_in[7];
    const float* qnw    = (const float*)d_in[8];
    const float* knw    = (const float*)d_in[9];
    float* out = (float*)d_out;

    float* qkv;
    cudaGetSymbolAddress((void**)&qkv, g_qkv);
    __half *hh, *wqkv, *wog, *gated;
    cudaGetSymbolAddress((void**)&hh,    g_hh);
    cudaGetSymbolAddress((void**)&wqkv,  g_wqkv);
    cudaGetSymbolAddress((void**)&wog,   g_wo);
    cudaGetSymbolAddress((void**)&gated, g_gated);

    cudaFuncSetAttribute(attn_mma_kernel,
                         cudaFuncAttributeMaxDynamicSharedMemorySize, ATT_SMEM);
    cudaFuncSetAttribute(gemm_fp16,
                         cudaFuncAttributeMaxDynamicSharedMemorySize, GSMEMF);

    const int M = B_ * S_;   // 8192

    // fp32 -> fp16 converts
    conv_kernel<<<(B_*S_*HID_)/1024, 256>>>(hidden, hh);
    conv_off_kernel<<<(HID_*H_*2*D_)/1024, 256>>>(wq, wqkv, H_*2*D_, 0);
    conv_off_kernel<<<(HID_*KV_*D_)/1024, 256>>>(wk, wqkv, KV_*D_, 4096);
    conv_off_kernel<<<(HID_*KV_*D_)/1024, 256>>>(wv, wqkv, KV_*D_, 4608);
    conv_kernel<<<(H_*D_*HID_)/1024, 256>>>(wo, wog);

    // merged QKV projection (fp16 tensor cores)
    gemm_fp16<<<dim3(NQKV/128, M/128), 256, GSMEMF>>>(hh, wqkv, qkv, M, NQKV, HID_);

    // norms + rope -> fp16 (Q pre-scaled, hi/lo; K,V single)
    norm_rope_kernel<<<dim3(M, 5), 128>>>(cosb, sinb, qnw, knw);

    // fp16 attention (+ fused sigmoid gate)
    attn_mma_kernel<<<dim3(B_*H_, S_/128), 256, ATT_SMEM>>>();

    // output projection (fp16 tensor cores)
    gemm_fp16<<<dim3(HID_/128, M/128), 256, GSMEMF>>>(gated, wog, out, M, HID_, H_*D_);
}

// round 17
// speedup vs baseline: 2.0603x; 1.0653x over previous
#include <cuda_runtime.h>
#include <cuda_bf16.h>
#include <cuda_fp16.h>
#include <math.h>
#include <stdint.h>

#define B_ 4
#define S_ 2048
#define HID_ 2048
#define H_ 16
#define KV_ 4
#define D_ 128
#define ROT_ 32
#define NEG_ (-1000000000.0f)
#define SCALE_ 0.08838834764831845f   // D^-0.5
#define NQKV 5120                     // merged projection width

// ---------------- scratch (device globals; no allocations allowed) ----------
__device__ float g_qkv  [(size_t)B_*S_*NQKV];      // [M, 5120] q|gate|k|v
__device__ __half g_hh   [(size_t)B_*S_*HID_];     // hidden fp16
__device__ __half g_wqkv [(size_t)HID_*NQKV];      // merged W fp16 [K, 5120]
__device__ __half g_wo   [(size_t)H_*D_*HID_];     // Wo fp16 [2048, 2048]
__device__ __half g_gated[(size_t)B_*S_*H_*D_];    // gated attn fp16
__device__ __half g_qh  [(size_t)B_*H_*S_*D_];     // q fp16
__device__ __half g_kf  [(size_t)B_*KV_*S_*D_];    // k fp16
__device__ __half g_vf  [(size_t)B_*KV_*S_*D_];    // v fp16

// ---------------- helpers -----------------------------------------------------
__device__ __forceinline__ uint32_t smem_u32(const void* p) {
    return (uint32_t)__cvta_generic_to_shared(p);
}
__device__ __forceinline__ void ldm_x4(uint32_t* r, uint32_t addr) {
    asm volatile("ldmatrix.sync.aligned.m8n8.x4.shared.b16 {%0,%1,%2,%3}, [%4];\n"
                 : "=r"(r[0]), "=r"(r[1]), "=r"(r[2]), "=r"(r[3]) : "r"(addr));
}
__device__ __forceinline__ void ldm_x4_t(uint32_t* r, uint32_t addr) {
    asm volatile("ldmatrix.sync.aligned.m8n8.x4.trans.shared.b16 {%0,%1,%2,%3}, [%4];\n"
                 : "=r"(r[0]), "=r"(r[1]), "=r"(r[2]), "=r"(r[3]) : "r"(addr));
}
__device__ __forceinline__ void mma_f16(float* c, const uint32_t* a,
                                        uint32_t b0, uint32_t b1) {
    asm volatile(
        "mma.sync.aligned.m16n8k16.row.col.f32.f16.f16.f32 "
        "{%0,%1,%2,%3}, {%4,%5,%6,%7}, {%8,%9}, {%0,%1,%2,%3};\n"
        : "+f"(c[0]), "+f"(c[1]), "+f"(c[2]), "+f"(c[3])
        : "r"(a[0]), "r"(a[1]), "r"(a[2]), "r"(a[3]), "r"(b0), "r"(b1));
}
__device__ __forceinline__ void mma_f16_s(float* c, uint32_t a0, uint32_t a1,
                                          uint32_t a2, uint32_t a3,
                                          uint32_t b0, uint32_t b1) {
    asm volatile(
        "mma.sync.aligned.m16n8k16.row.col.f32.f16.f16.f32 "
        "{%0,%1,%2,%3}, {%4,%5,%6,%7}, {%8,%9}, {%0,%1,%2,%3};\n"
        : "+f"(c[0]), "+f"(c[1]), "+f"(c[2]), "+f"(c[3])
        : "r"(a0), "r"(a1), "r"(a2), "r"(a3), "r"(b0), "r"(b1));
}
__device__ __forceinline__ uint32_t h2_u32(__half2 v) {
    return *reinterpret_cast<uint32_t*>(&v);
}
__device__ __forceinline__ void cpa16(uint32_t dst, const void* src) {
    asm volatile("cp.async.cg.shared.global [%0], [%1], 16;\n"
                 :: "r"(dst), "l"(src));
}

// ---------------- convert fp32 -> fp16 (contiguous) ---------------------------
__global__ __launch_bounds__(256)
void conv_kernel(const float* __restrict__ src, __half* __restrict__ dst) {
    size_t i = (size_t)blockIdx.x * 256 + threadIdx.x;
    float4 v = ((const float4*)src)[i];
    __half2 h0 = __floats2half2_rn(v.x, v.y);
    __half2 h1 = __floats2half2_rn(v.z, v.w);
    ((uint2*)dst)[i] = make_uint2(h2_u32(h0), h2_u32(h1));
}

// ---------------- convert with column offset into merged weight buffer -------
__global__ __launch_bounds__(256)
void conv_off_kernel(const float* __restrict__ src, __half* __restrict__ dst,
                     int ncols, int coloff) {
    size_t i = (size_t)blockIdx.x * 256 + threadIdx.x;
    int c4 = ncols >> 2;
    int row = (int)(i / c4), col = (int)(i % c4) << 2;
    float4 v = ((const float4*)src)[i];
    __half2 h0 = __floats2half2_rn(v.x, v.y);
    __half2 h1 = __floats2half2_rn(v.z, v.w);
    size_t o = ((size_t)row * NQKV + coloff + col) >> 2;
    ((uint2*)dst)[o] = make_uint2(h2_u32(h0), h2_u32(h1));
}

// ---------------- fp16 tensor-core GEMM, 128x128x32, 256 thr, 2-stage --------
#define ASTR 40
#define BSTR 136
#define A_ELE (128*ASTR)
#define B_ELE (32*BSTR)
#define FSTG (A_ELE + B_ELE)
#define GSMEMF (2*FSTG*2)

__global__ __launch_bounds__(256)
void gemm_fp16(const __half* __restrict__ A, const __half* __restrict__ B,
               float* __restrict__ C, int M, int N, int K) {
    extern __shared__ __half fsm[];
    int tid = threadIdx.x;
    int warp = tid >> 5, lane = tid & 31;
    int wm = (warp >> 2) * 64;
    int wn = (warp & 3) * 32;

    const __half* Ab = A + (size_t)blockIdx.y * 128 * K;
    const __half* Bb = B + (size_t)blockIdx.x * 128;

    float acc[4][4][4];
    #pragma unroll
    for (int mt = 0; mt < 4; mt++)
        #pragma unroll
        for (int nt = 0; nt < 4; nt++)
            #pragma unroll
            for (int i = 0; i < 4; i++) acc[mt][nt][i] = 0.f;

    int KT = K >> 5;

    auto issue = [&](int kt, int st) {
        __half* s = fsm + st * FSTG;
        int k0 = kt << 5;
        #pragma unroll
        for (int c = tid; c < 512; c += 256) {
            int row = c >> 2, col = (c & 3) << 3;
            cpa16(smem_u32(s + row * ASTR + col), Ab + (size_t)row * K + k0 + col);
        }
        #pragma unroll
        for (int c = tid; c < 512; c += 256) {
            int row = c >> 4, col = (c & 15) << 3;
            cpa16(smem_u32(s + A_ELE + row * BSTR + col), Bb + (size_t)(k0 + row) * N + col);
        }
        asm volatile("cp.async.commit_group;\n" ::: "memory");
    };

    issue(0, 0);
    for (int kt = 0; kt < KT; kt++) {
        asm volatile("cp.async.wait_group 0;\n" ::: "memory");
        __syncthreads();
        if (kt + 1 < KT) issue(kt + 1, (kt + 1) & 1);

        __half* s = fsm + (kt & 1) * FSTG;
        __half* sA = s;
        __half* sB = s + A_ELE;

        #pragma unroll
        for (int ks = 0; ks < 2; ks++) {
            int kk = ks * 16;
            uint32_t af[4][4];
            #pragma unroll
            for (int mt = 0; mt < 4; mt++) {
                int row = wm + mt * 16 + (lane & 15);
                int col = kk + ((lane >> 4) << 3);
                ldm_x4(af[mt], smem_u32(&sA[row * ASTR + col]));
            }
            uint32_t bf[2][4];
            #pragma unroll
            for (int nc = 0; nc < 2; nc++) {
                int row = kk + (lane & 15);
                int col = wn + nc * 16 + ((lane >> 4) << 3);
                ldm_x4_t(bf[nc], smem_u32(&sB[row * BSTR + col]));
            }
            #pragma unroll
            for (int mt = 0; mt < 4; mt++) {
                #pragma unroll
                for (int nt = 0; nt < 4; nt++) {
                    int nc = nt >> 1, off = (nt & 1) << 1;
                    mma_f16(acc[mt][nt], af[mt], bf[nc][off], bf[nc][off + 1]);
                }
            }
        }
        __syncthreads();
    }

    float* Cb = C + (size_t)blockIdx.y * 128 * N + (size_t)blockIdx.x * 128;
    #pragma unroll
    for (int mt = 0; mt < 4; mt++) {
        #pragma unroll
        for (int nt = 0; nt < 4; nt++) {
            int r = wm + mt * 16 + (lane >> 2);
            int c = wn + nt * 8 + ((lane & 3) << 1);
            *(float2*)&Cb[(size_t)r * N + c] = make_float2(acc[mt][nt][0], acc[mt][nt][1]);
            *(float2*)&Cb[(size_t)(r + 8) * N + c] = make_float2(acc[mt][nt][2], acc[mt][nt][3]);
        }
    }
}

// ---------------- merged RMSNorm + RoPE, parallel over head groups ----------
__global__ __launch_bounds__(128)
void norm_rope_kernel(const float* __restrict__ cosb, const float* __restrict__ sinb,
                      const float* __restrict__ qw, const float* __restrict__ kw) {
    int bs = blockIdx.x, grp = blockIdx.y, d = threadIdx.x;
    float cthis = 0.f, sthis = 0.f;
    if (d < ROT_) {
        cthis = cosb[(size_t)bs * ROT_ + d];
        sthis = sinb[(size_t)bs * ROT_ + d];
    }
    int b = bs / S_, s = bs % S_;
    int warp = d >> 5, lane = d & 31;
    __shared__ float ws[4];
    const float* rowp = g_qkv + (size_t)bs * NQKV;

    if (grp < 4) {
        float qwd = 1.f + qw[d];
        #pragma unroll
        for (int hh = 0; hh < 4; hh++) {
            int h = grp * 4 + hh;
            float x = rowp[h * (2*D_) + d];
            float v = x * x;
            #pragma unroll
            for (int off = 16; off; off >>= 1) v += __shfl_xor_sync(0xffffffffu, v, off);
            if (lane == 0) ws[warp] = v;
            __syncthreads();
            float tot = ws[0] + ws[1] + ws[2] + ws[3];
            __syncthreads();

            float xn = x * rsqrtf(tot * (1.f/128.f) + 1e-6f) * qwd;
            float o = xn;
            if (d < ROT_) {
                float xp = __shfl_xor_sync(0xffffffffu, xn, 16);
                float rot = (d < 16) ? -xp : xp;
                o = xn * cthis + rot * sthis;
            }
            o *= SCALE_;
            size_t idx = (((size_t)b * H_ + h) * S_ + s) * D_ + d;
            g_qh[idx] = __float2half(o);
        }
    } else {
        float kwd = 1.f + kw[d];
        #pragma unroll
        for (int kv = 0; kv < KV_; kv++) {
            float x = rowp[4096 + kv * D_ + d];
            float v = x * x;
            #pragma unroll
            for (int off = 16; off; off >>= 1) v += __shfl_xor_sync(0xffffffffu, v, off);
            if (lane == 0) ws[warp] = v;
            __syncthreads();
            float tot = ws[0] + ws[1] + ws[2] + ws[3];
            __syncthreads();

            float xn = x * rsqrtf(tot * (1.f/128.f) + 1e-6f) * kwd;
            float o = xn;
            if (d < ROT_) {
                float xp = __shfl_xor_sync(0xffffffffu, xn, 16);
                float rot = (d < 16) ? -xp : xp;
                o = xn * cthis + rot * sthis;
            }
            size_t oidx = (((size_t)b * KV_ + kv) * S_ + s) * D_ + d;
            g_kf[oidx] = __float2half(o);
            g_vf[oidx] = __float2half(rowp[4608 + kv * D_ + d]);
        }
    }
}

// ---------------- fp16 flash attention, cp.async double-buffered K/V --------
// QK: q single x k single (1 mma); PV: p single x v single (1 mma).
// Q smem single -> 102 KB total -> 2 CTAs/SM.
#define AQS 136
#define KVST (2*64*AQS)                     // K + V per stage (fp16 elems)
#define ATT_SMEM ((128*AQS + 2*KVST) * 2)   // bytes (~102 KB)

__global__ __launch_bounds__(256)
void attn_mma_kernel() {
    extern __shared__ __align__(16) __half smA[];
    __half* sQ  = smA;
    __half* sKV = sQ + 128 * AQS;   // 2 stages x [K|V]

    int tid = threadIdx.x, warp = tid >> 5, lane = tid & 31;
    int bh = blockIdx.x;
    int qt = (int)gridDim.y - 1 - (int)blockIdx.y;   // LPT
    int b = bh >> 4, h = bh & 15, kvh = h >> 2;

    size_t qoff = ((size_t)bh * S_ + (size_t)qt * 128) * D_;
    size_t kvoff = ((size_t)(b * KV_ + kvh) * S_) * D_;

    for (int i = tid; i < 2048; i += 256) {
        int r = i >> 4, c = (i & 15) << 3;
        *(uint4*)&sQ[r * AQS + c] = *(const uint4*)&g_qh[qoff + (size_t)r * D_ + c];
    }

    auto issue_kv = [&](int kt, int st) {
        __half* s = sKV + st * KVST;
        size_t koff = kvoff + (size_t)kt * 64 * D_;
        #pragma unroll
        for (int i = tid; i < 1024; i += 256) {
            int r = i >> 4, c = (i & 15) << 3;
            size_t g = koff + (size_t)r * D_ + c;
            int sidx = r * AQS + c;
            cpa16(smem_u32(s + sidx), &g_kf[g]);
            cpa16(smem_u32(s + 64*AQS + sidx), &g_vf[g]);
        }
    };

    float acc[16][4];
    #pragma unroll
    for (int ot = 0; ot < 16; ot++)
        #pragma unroll
        for (int i = 0; i < 4; i++) acc[ot][i] = 0.f;
    float m0 = -1e30f, m1 = -1e30f, l0 = 0.f, l1 = 0.f;

    int nkt = 2 * qt + 2;
    issue_kv(0, 0);
    asm volatile("cp.async.commit_group;\n" ::: "memory");

    for (int kt = 0; kt < nkt; kt++) {
        if (kt + 1 < nkt) issue_kv(kt + 1, (kt + 1) & 1);
        asm volatile("cp.async.commit_group;\n" ::: "memory");
        asm volatile("cp.async.wait_group 1;\n" ::: "memory");
        __syncthreads();

        if (kt * 64 > qt * 128 + warp * 16 + 15) {
            __syncthreads();
            continue;
        }

        __half* s = sKV + (kt & 1) * KVST;
        __half* sK = s;
        __half* sV = s + 64*AQS;

        float sc[8][4];
        #pragma unroll
        for (int nt = 0; nt < 8; nt++)
            #pragma unroll
            for (int i = 0; i < 4; i++) sc[nt][i] = 0.f;

        #pragma unroll
        for (int kk = 0; kk < 8; kk++) {
            uint32_t aq[4];
            int qidx = (warp * 16 + (lane & 15)) * AQS + kk * 16 + ((lane >> 4) << 3);
            ldm_x4(aq, smem_u32(&sQ[qidx]));
            #pragma unroll
            for (int nc = 0; nc < 4; nc++) {
                uint32_t k4[4];
                int kidx = (nc * 16 + (lane & 15)) * AQS + kk * 16 + ((lane >> 4) << 3);
                ldm_x4(k4, smem_u32(&sK[kidx]));
                #pragma unroll
                for (int hf = 0; hf < 2; hf++) {
                    int nt = nc * 2 + hf;
                    mma_f16(sc[nt], aq, k4[hf], k4[hf + 2]);
                }
            }
        }

        int row0 = qt * 128 + warp * 16 + (lane >> 2);
        int col0 = kt * 64 + ((lane & 3) << 1);
        float ml0 = -1e30f, ml1 = -1e30f;
        bool needmask = (kt * 64 + 63) > (qt * 128 + warp * 16);
        if (needmask) {
            #pragma unroll
            for (int nt = 0; nt < 8; nt++) {
                int c0 = col0 + nt * 8;
                float v0 = sc[nt][0] + ((c0    ) > row0     ? NEG_ : 0.f);
                float v1 = sc[nt][1] + ((c0 + 1) > row0     ? NEG_ : 0.f);
                float v2 = sc[nt][2] + ((c0    ) > row0 + 8 ? NEG_ : 0.f);
                float v3 = sc[nt][3] + ((c0 + 1) > row0 + 8 ? NEG_ : 0.f);
                sc[nt][0] = v0; sc[nt][1] = v1; sc[nt][2] = v2; sc[nt][3] = v3;
                ml0 = fmaxf(ml0, fmaxf(v0, v1));
                ml1 = fmaxf(ml1, fmaxf(v2, v3));
            }
        } else {
            #pragma unroll
            for (int nt = 0; nt < 8; nt++) {
                ml0 = fmaxf(ml0, fmaxf(sc[nt][0], sc[nt][1]));
                ml1 = fmaxf(ml1, fmaxf(sc[nt][2], sc[nt][3]));
            }
        }
        ml0 = fmaxf(ml0, __shfl_xor_sync(0xffffffffu, ml0, 1));
        ml0 = fmaxf(ml0, __shfl_xor_sync(0xffffffffu, ml0, 2));
        ml1 = fmaxf(ml1, __shfl_xor_sync(0xffffffffu, ml1, 1));
        ml1 = fmaxf(ml1, __shfl_xor_sync(0xffffffffu, ml1, 2));
        float nm0 = fmaxf(m0, ml0), nm1 = fmaxf(m1, ml1);
        bool rescale = (nm0 != m0) || (nm1 != m1);
        float corr0 = __expf(m0 - nm0), corr1 = __expf(m1 - nm1);
        m0 = nm0; m1 = nm1;

        uint32_t ph[8][2];
        float sum0 = 0.f, sum1 = 0.f;
        #pragma unroll
        for (int nt = 0; nt < 8; nt++) {
            float p0 = __expf(sc[nt][0] - nm0);
            float p1 = __expf(sc[nt][1] - nm0);
            float p2 = __expf(sc[nt][2] - nm1);
            float p3 = __expf(sc[nt][3] - nm1);
            sum0 += p0 + p1; sum1 += p2 + p3;
            ph[nt][0] = h2_u32(__floats2half2_rn(p0, p1));
            ph[nt][1] = h2_u32(__floats2half2_rn(p2, p3));
        }
        sum0 += __shfl_xor_sync(0xffffffffu, sum0, 1);
        sum0 += __shfl_xor_sync(0xffffffffu, sum0, 2);
        sum1 += __shfl_xor_sync(0xffffffffu, sum1, 1);
        sum1 += __shfl_xor_sync(0xffffffffu, sum1, 2);
        l0 = l0 * corr0 + sum0;
        l1 = l1 * corr1 + sum1;
        if (rescale) {   // corr==1 exactly when max unchanged -> skip is exact
            #pragma unroll
            for (int ot = 0; ot < 16; ot++) {
                acc[ot][0] *= corr0; acc[ot][1] *= corr0;
                acc[ot][2] *= corr1; acc[ot][3] *= corr1;
            }
        }

        #pragma unroll
        for (int k2 = 0; k2 < 4; k2++) {
            uint32_t a0 = ph[2*k2][0], a1 = ph[2*k2][1];
            uint32_t a2 = ph[2*k2+1][0], a3 = ph[2*k2+1][1];
            #pragma unroll
            for (int nc = 0; nc < 8; nc++) {
                uint32_t v4[4];
                int vidx = (k2 * 16 + (lane & 15)) * AQS + nc * 16 + ((lane >> 4) << 3);
                ldm_x4_t(v4, smem_u32(&sV[vidx]));
                #pragma unroll
                for (int hf = 0; hf < 2; hf++) {
                    int ot = nc * 2 + hf, of = hf * 2;
                    mma_f16_s(acc[ot], a0, a1, a2, a3, v4[of], v4[of + 1]);
                }
            }
        }
        __syncthreads();
    }

    // ---- epilogue: normalize, gate, write fp16 gated output
    float inv0 = 1.f / l0, inv1 = 1.f / l1;
    int srow = qt * 128 + warp * 16 + (lane >> 2);
    #pragma unroll
    for (int rp = 0; rp < 2; rp++) {
        int s = srow + rp * 8;
        size_t bs = (size_t)b * S_ + s;
        float inv = rp ? inv1 : inv0;
        #pragma unroll
        for (int ot = 0; ot < 16; ot++) {
            int c0 = ot * 8 + ((lane & 3) << 1);
            float2 g2 = *(const float2*)&g_qkv[bs * (size_t)NQKV + h * (2*D_) + D_ + c0];
            float o0 = acc[ot][rp*2    ] * inv * (1.f / (1.f + __expf(-g2.x)));
            float o1 = acc[ot][rp*2 + 1] * inv * (1.f / (1.f + __expf(-g2.y)));
            __half2 h2 = __floats2half2_rn(o0, o1);
            size_t oi = bs * (size_t)(H_*D_) + h * D_ + c0;
            *(uint32_t*)&g_gated[oi] = h2_u32(h2);
        }
    }
}

// ---------------- launch ----------------------------------------------------
extern "C" void kernel_launch(void* const* d_in, const int* in_sizes, int n_in,
                              void* d_out, int out_size) {
    const float* hidden = (const float*)d_in[0];
    const float* cosb   = (const float*)d_in[1];
    const float* sinb   = (const float*)d_in[2];
    // d_in[3] = attention_mask (pure causal; computed arithmetically)
    const float* wq     = (const float*)d_in[4];
    const float* wk     = (const float*)d_in[5];
    const float* wv     = (const float*)d_in[6];
    const float* wo     = (const float*)d_in[7];
    const float* qnw    = (const float*)d_in[8];
    const float* knw    = (const float*)d_in[9];
    float* out = (float*)d_out;

    float* qkv;
    cudaGetSymbolAddress((void**)&qkv, g_qkv);
    __half *hh, *wqkv, *wog, *gated;
    cudaGetSymbolAddress((void**)&hh,    g_hh);
    cudaGetSymbolAddress((void**)&wqkv,  g_wqkv);
    cudaGetSymbolAddress((void**)&wog,   g_wo);
    cudaGetSymbolAddress((void**)&gated, g_gated);

    cudaFuncSetAttribute(attn_mma_kernel,
                         cudaFuncAttributeMaxDynamicSharedMemorySize, ATT_SMEM);
    cudaFuncSetAttribute(gemm_fp16,
                         cudaFuncAttributeMaxDynamicSharedMemorySize, GSMEMF);

    const int M = B_ * S_;   // 8192

    // fp32 -> fp16 converts
    conv_kernel<<<(B_*S_*HID_)/1024, 256>>>(hidden, hh);
    conv_off_kernel<<<(HID_*H_*2*D_)/1024, 256>>>(wq, wqkv, H_*2*D_, 0);
    conv_off_kernel<<<(HID_*KV_*D_)/1024, 256>>>(wk, wqkv, KV_*D_, 4096);
    conv_off_kernel<<<(HID_*KV_*D_)/1024, 256>>>(wv, wqkv, KV_*D_, 4608);
    conv_kernel<<<(H_*D_*HID_)/1024, 256>>>(wo, wog);

    // merged QKV projection (fp16 tensor cores)
    gemm_fp16<<<dim3(NQKV/128, M/128), 256, GSMEMF>>>(hh, wqkv, qkv, M, NQKV, HID_);

    // norms + rope -> fp16 (Q pre-scaled)
    norm_rope_kernel<<<dim3(M, 5), 128>>>(cosb, sinb, qnw, knw);

    // fp16 attention (+ fused sigmoid gate), 2 CTAs/SM
    attn_mma_kernel<<<dim3(B_*H_, S_/128), 256, ATT_SMEM>>>();

    // output projection (fp16 tensor cores)
    gemm_fp16<<<dim3(HID_/128, M/128), 256, GSMEMF>>>(gated, wog, out, M, HID_, H_*D_);
}